// round 1
// baseline (speedup 1.0000x reference)
#include <cuda_runtime.h>

#define BATCH 8
#define EMBD  1024
#define CIND  512
#define NTOK  1024
#define SEQL  1024

// Scratch (device globals; allocation-free). g_XT is reused for O.
__device__ float g_XT[(size_t)BATCH * EMBD * NTOK];
__device__ float g_Q [(size_t)BATCH * EMBD * NTOK];
__device__ float g_K [(size_t)BATCH * EMBD * SEQL];
__device__ float g_V [(size_t)BATCH * EMBD * SEQL];

// ---------------------------------------------------------------------------
// Batched SGEMM: C[b] = alpha * A[b] * B[b] (+ bias per M-row)
//   A layout: A_KM ? A[k*lda + m] : A[m*lda + k]
//   B layout: B_NK ? B[n*ldb + k] : B[k*ldb + n]
// Tile 128x128, BK=8, 256 threads, 8x8 register tile per thread.
// All of M, N multiples of 128; K multiple of 8. Pointers 16B aligned.
// ---------------------------------------------------------------------------
template<bool A_KM, bool B_NK, bool HAS_BIAS>
__global__ __launch_bounds__(256) void sgemm_k(
    const float* __restrict__ Ag, const float* __restrict__ Bg,
    float* __restrict__ Cg, const float* __restrict__ bias,
    int K, int lda, int ldb, int ldc,
    size_t sA, size_t sB, size_t sC, float alpha)
{
    __shared__ float As[8][128];
    __shared__ float Bs[8][128];

    const int b = blockIdx.z;
    const float* A = Ag + (size_t)b * sA;
    const float* B = Bg + (size_t)b * sB;
    float*       C = Cg + (size_t)b * sC;

    const int m0  = blockIdx.y * 128;
    const int n0  = blockIdx.x * 128;
    const int tid = threadIdx.x;
    const int ty  = tid >> 4;   // 0..15
    const int tx  = tid & 15;   // 0..15

    float acc[8][8] = {};

    for (int kt = 0; kt < K; kt += 8) {
        // ---- load A tile into As[k][m] ----
        if (A_KM) {
            int k  = tid >> 5;            // 0..7
            int m4 = (tid & 31) << 2;     // 0..124
            float4 v = *reinterpret_cast<const float4*>(
                &A[(size_t)(kt + k) * lda + m0 + m4]);
            *reinterpret_cast<float4*>(&As[k][m4]) = v;
        } else {
            int m  = tid >> 1;            // 0..127
            int kk = (tid & 1) << 2;      // 0 or 4
            float4 v = *reinterpret_cast<const float4*>(
                &A[(size_t)(m0 + m) * lda + kt + kk]);
            As[kk + 0][m] = v.x; As[kk + 1][m] = v.y;
            As[kk + 2][m] = v.z; As[kk + 3][m] = v.w;
        }
        // ---- load B tile into Bs[k][n] ----
        if (B_NK) {
            int n  = tid >> 1;
            int kk = (tid & 1) << 2;
            float4 v = *reinterpret_cast<const float4*>(
                &B[(size_t)(n0 + n) * ldb + kt + kk]);
            Bs[kk + 0][n] = v.x; Bs[kk + 1][n] = v.y;
            Bs[kk + 2][n] = v.z; Bs[kk + 3][n] = v.w;
        } else {
            int k  = tid >> 5;
            int n4 = (tid & 31) << 2;
            float4 v = *reinterpret_cast<const float4*>(
                &B[(size_t)(kt + k) * ldb + n0 + n4]);
            *reinterpret_cast<float4*>(&Bs[k][n4]) = v;
        }
        __syncthreads();

        #pragma unroll
        for (int k = 0; k < 8; k++) {
            float a[8], bb[8];
            *reinterpret_cast<float4*>(a)      = *reinterpret_cast<float4*>(&As[k][ty * 8]);
            *reinterpret_cast<float4*>(a + 4)  = *reinterpret_cast<float4*>(&As[k][ty * 8 + 4]);
            *reinterpret_cast<float4*>(bb)     = *reinterpret_cast<float4*>(&Bs[k][tx * 8]);
            *reinterpret_cast<float4*>(bb + 4) = *reinterpret_cast<float4*>(&Bs[k][tx * 8 + 4]);
            #pragma unroll
            for (int i = 0; i < 8; i++)
                #pragma unroll
                for (int j = 0; j < 8; j++)
                    acc[i][j] += a[i] * bb[j];
        }
        __syncthreads();
    }

    // ---- epilogue ----
    #pragma unroll
    for (int i = 0; i < 8; i++) {
        int m = m0 + ty * 8 + i;
        float bv = HAS_BIAS ? bias[m] : 0.0f;
        #pragma unroll
        for (int j = 0; j < 8; j += 4) {
            float4 o;
            o.x = alpha * acc[i][j + 0] + bv;
            o.y = alpha * acc[i][j + 1] + bv;
            o.z = alpha * acc[i][j + 2] + bv;
            o.w = alpha * acc[i][j + 3] + bv;
            *reinterpret_cast<float4*>(&C[(size_t)m * ldc + n0 + tx * 8 + j]) = o;
        }
    }
}

// ---------------------------------------------------------------------------
// In-place masked softmax over rows of length SEQL (=1024).
// One block of 256 threads per row; 4 elements per thread.
// ---------------------------------------------------------------------------
__global__ __launch_bounds__(256) void softmax_rows(
    float* __restrict__ S, const unsigned char* __restrict__ mask)
{
    const size_t row = blockIdx.x;
    float4* p = reinterpret_cast<float4*>(S + row * SEQL);
    const uchar4* mp = reinterpret_cast<const uchar4*>(mask + row * SEQL);
    const int t = threadIdx.x;

    float4 v = p[t];
    uchar4 m = mp[t];
    if (m.x) v.x = -1e9f;
    if (m.y) v.y = -1e9f;
    if (m.z) v.z = -1e9f;
    if (m.w) v.w = -1e9f;

    float mx = fmaxf(fmaxf(v.x, v.y), fmaxf(v.z, v.w));
    #pragma unroll
    for (int o = 16; o; o >>= 1) mx = fmaxf(mx, __shfl_xor_sync(0xffffffffu, mx, o));
    __shared__ float sm[8];
    const int w = t >> 5;
    if ((t & 31) == 0) sm[w] = mx;
    __syncthreads();
    float rmax = sm[0];
    #pragma unroll
    for (int i = 1; i < 8; i++) rmax = fmaxf(rmax, sm[i]);

    v.x = __expf(v.x - rmax);
    v.y = __expf(v.y - rmax);
    v.z = __expf(v.z - rmax);
    v.w = __expf(v.w - rmax);

    float s = v.x + v.y + v.z + v.w;
    #pragma unroll
    for (int o = 16; o; o >>= 1) s += __shfl_xor_sync(0xffffffffu, s, o);
    __shared__ float ss[8];
    if ((t & 31) == 0) ss[w] = s;
    __syncthreads();
    float tot = 0.0f;
    #pragma unroll
    for (int i = 0; i < 8; i++) tot += ss[i];

    float inv = 1.0f / tot;
    v.x *= inv; v.y *= inv; v.z *= inv; v.w *= inv;
    p[t] = v;
}

// ---------------------------------------------------------------------------
extern "C" void kernel_launch(void* const* d_in, const int* in_sizes, int n_in,
                              void* d_out, int out_size)
{
    const float* x        = (const float*)d_in[0];  // (8,512,32,32)
    const float* content  = (const float*)d_in[1];  // (8,1024,1024)
    const unsigned char* pmask = (const unsigned char*)d_in[2]; // (8,1024,1024) bool
    const float* W_in     = (const float*)d_in[3];  // (1024,512)
    const float* b_in     = (const float*)d_in[4];  // (1024,)
    const float* Wq       = (const float*)d_in[5];  // (1024,1024)
    const float* Wk       = (const float*)d_in[6];
    const float* Wv       = (const float*)d_in[7];
    const float* W_out    = (const float*)d_in[8];  // (512,1024)
    const float* b_out    = (const float*)d_in[9];  // (512,)

    float* out = (float*)d_out;                          // (8,512,32,32)
    float* att = out + (size_t)BATCH * CIND * NTOK;      // (8,1024,1024)

    float *XT, *Q, *Kp, *Vp;
    cudaGetSymbolAddress((void**)&XT, g_XT);
    cudaGetSymbolAddress((void**)&Q,  g_Q);
    cudaGetSymbolAddress((void**)&Kp, g_K);
    cudaGetSymbolAddress((void**)&Vp, g_V);

    const float scale = 1.0f / 32.0f;  // EMB^-0.5 with EMB=1024
    const size_t EN = (size_t)EMBD * NTOK;   // 1M elems per batch
    const size_t SE = (size_t)SEQL * EMBD;
    const size_t NS = (size_t)NTOK * SEQL;
    dim3 g88(NTOK / 128, EMBD / 128, BATCH);

    // 1. XT[e,n] = sum_c W_in[e,c] * x[b,c,n] + b_in[e]
    sgemm_k<false, false, true><<<g88, 256>>>(
        W_in, x, XT, b_in, CIND, CIND, NTOK, NTOK,
        0, (size_t)CIND * NTOK, EN, 1.0f);

    // 2. Q[e,n] = sum_d Wq[e,d] * XT[d,n]
    sgemm_k<false, false, false><<<g88, 256>>>(
        Wq, XT, Q, nullptr, EMBD, EMBD, NTOK, NTOK,
        0, EN, EN, 1.0f);

    // 3. K[e,s] = sum_d Wk[e,d] * content[b,s,d]
    sgemm_k<false, true, false><<<dim3(SEQL / 128, EMBD / 128, BATCH), 256>>>(
        Wk, content, Kp, nullptr, EMBD, EMBD, EMBD, SEQL,
        0, SE, SE, 1.0f);

    // 4. V[e,s]
    sgemm_k<false, true, false><<<dim3(SEQL / 128, EMBD / 128, BATCH), 256>>>(
        Wv, content, Vp, nullptr, EMBD, EMBD, EMBD, SEQL,
        0, SE, SE, 1.0f);

    // 5. S[i,j] = scale * sum_e Q[e,i] * K[e,j]  -> att region of d_out
    sgemm_k<true, false, false><<<dim3(SEQL / 128, NTOK / 128, BATCH), 256>>>(
        Q, Kp, att, nullptr, EMBD, NTOK, SEQL, SEQL,
        EN, SE, NS, scale);

    // 6. masked softmax in place on att
    softmax_rows<<<BATCH * NTOK, 256>>>(att, pmask);

    // 7. O[d,i] = sum_j V[d,j] * att[i,j]   (reuse XT scratch)
    sgemm_k<false, true, false><<<dim3(NTOK / 128, EMBD / 128, BATCH), 256>>>(
        Vp, att, XT, nullptr, SEQL, SEQL, SEQL, NTOK,
        SE, NS, EN, 1.0f);

    // 8. out[c,n] = sum_e W_out[c,e] * O[e,n] + b_out[c]
    sgemm_k<false, false, true><<<dim3(NTOK / 128, CIND / 128, BATCH), 256>>>(
        W_out, XT, out, b_out, EMBD, EMBD, NTOK, NTOK,
        0, EN, (size_t)CIND * NTOK, 1.0f);
}

// round 2
// speedup vs baseline: 2.2703x; 2.2703x over previous
#include <cuda_runtime.h>
#include <cstdint>

#define BATCH 8
#define EMBD  1024
#define CIND  512
#define NTOK  1024
#define SEQL  1024

// Scratch (device globals; allocation-free). g_XT is reused for O.
__device__ float g_XT[(size_t)BATCH * EMBD * NTOK];
__device__ float g_Q [(size_t)BATCH * EMBD * NTOK];
__device__ float g_K [(size_t)BATCH * EMBD * SEQL];
__device__ float g_V [(size_t)BATCH * EMBD * SEQL];

// f32 -> tf32 with round-to-nearest (done once per element at smem store)
__device__ __forceinline__ uint32_t f2tf(float x) {
    uint32_t r;
    asm("cvt.rna.tf32.f32 %0, %1;" : "=r"(r) : "f"(x));
    return r;
}

__device__ __forceinline__ void mma_tf32(float* d, const uint32_t* a, const uint32_t* b) {
    asm volatile(
        "mma.sync.aligned.m16n8k8.row.col.f32.tf32.tf32.f32 "
        "{%0,%1,%2,%3}, {%4,%5,%6,%7}, {%8,%9}, {%0,%1,%2,%3};"
        : "+f"(d[0]), "+f"(d[1]), "+f"(d[2]), "+f"(d[3])
        : "r"(a[0]), "r"(a[1]), "r"(a[2]), "r"(a[3]), "r"(b[0]), "r"(b[1]));
}

// ---------------------------------------------------------------------------
// Batched TF32 tensor-core GEMM: C[b] = alpha * A[b] * B[b] (+ bias per M-row)
//   A layout: A_KM ? A[k*lda + m] : A[m*lda + k]
//   B layout: B_NK ? B[n*ldb + k] : B[k*ldb + n]
// Block tile 128x128, BK=16, 256 threads (8 warps, 4x2), warp tile 32x64.
// Smem swizzle: element (k, m) stored at k*128 + (m ^ ((k&3)<<3)) --> all
// fragment LDS and the float4 STS are bank-conflict free.
// M, N multiples of 128; K multiple of 16.
// ---------------------------------------------------------------------------
template<bool A_KM, bool B_NK, bool HAS_BIAS>
__global__ __launch_bounds__(256) void mm_tf32(
    const float* __restrict__ Ag, const float* __restrict__ Bg,
    float* __restrict__ Cg, const float* __restrict__ bias,
    int K, int lda, int ldb, int ldc,
    size_t sA, size_t sB, size_t sC, float alpha)
{
    __shared__ uint32_t As[16 * 128];
    __shared__ uint32_t Bs[16 * 128];

    const int bz = blockIdx.z;
    const float* A = Ag + (size_t)bz * sA;
    const float* B = Bg + (size_t)bz * sB;
    float*       C = Cg + (size_t)bz * sC;

    const int m0 = blockIdx.y * 128;
    const int n0 = blockIdx.x * 128;
    const int tid  = threadIdx.x;
    const int wid  = tid >> 5;
    const int lane = tid & 31;
    const int g = lane >> 2;      // group id 0..7
    const int t = lane & 3;       // thread-in-group 0..3
    const int m0w = (wid & 3) * 32;   // warp m offset in block
    const int n0w = (wid >> 2) * 64;  // warp n offset in block

    // Precomputed swizzled smem offsets (k0 added as 0/8, +512 selects k+4)
    int aoff[2][2], boff[8];
    #pragma unroll
    for (int mt = 0; mt < 2; mt++) {
        aoff[mt][0] = t * 128 + ((m0w + mt * 16 + g)     ^ (t << 3));
        aoff[mt][1] = t * 128 + ((m0w + mt * 16 + 8 + g) ^ (t << 3));
    }
    #pragma unroll
    for (int nt = 0; nt < 8; nt++)
        boff[nt] = t * 128 + ((n0w + nt * 8 + g) ^ (t << 3));

    float acc[2][8][4];
    #pragma unroll
    for (int mt = 0; mt < 2; mt++)
        #pragma unroll
        for (int nt = 0; nt < 8; nt++)
            #pragma unroll
            for (int i = 0; i < 4; i++) acc[mt][nt][i] = 0.0f;

    float4 pa[2], pb[2];

    auto loadA = [&](int kt) {
        #pragma unroll
        for (int i = 0; i < 2; i++) {
            int f = tid + i * 256;
            if (A_KM) {
                int k = f >> 5, m4 = (f & 31) << 2;
                pa[i] = *reinterpret_cast<const float4*>(
                    &A[(size_t)(kt + k) * lda + m0 + m4]);
            } else {
                int m = f >> 2, kq = (f & 3) << 2;
                pa[i] = *reinterpret_cast<const float4*>(
                    &A[(size_t)(m0 + m) * lda + kt + kq]);
            }
        }
    };
    auto loadB = [&](int kt) {
        #pragma unroll
        for (int i = 0; i < 2; i++) {
            int f = tid + i * 256;
            if (B_NK) {
                int n = f >> 2, kq = (f & 3) << 2;
                pb[i] = *reinterpret_cast<const float4*>(
                    &B[(size_t)(n0 + n) * ldb + kt + kq]);
            } else {
                int k = f >> 5, n4 = (f & 31) << 2;
                pb[i] = *reinterpret_cast<const float4*>(
                    &B[(size_t)(kt + k) * ldb + n0 + n4]);
            }
        }
    };
    auto storeA = [&]() {
        #pragma unroll
        for (int i = 0; i < 2; i++) {
            int f = tid + i * 256;
            if (A_KM) {
                int k = f >> 5, m4 = (f & 31) << 2;
                uint32_t* p = &As[k * 128 + (m4 ^ ((k & 3) << 3))];
                p[0] = f2tf(pa[i].x); p[1] = f2tf(pa[i].y);
                p[2] = f2tf(pa[i].z); p[3] = f2tf(pa[i].w);
            } else {
                int m = f >> 2, kq = (f & 3) << 2;
                float v[4] = {pa[i].x, pa[i].y, pa[i].z, pa[i].w};
                #pragma unroll
                for (int j = 0; j < 4; j++)
                    As[(kq + j) * 128 + (m ^ (j << 3))] = f2tf(v[j]);
            }
        }
    };
    auto storeB = [&]() {
        #pragma unroll
        for (int i = 0; i < 2; i++) {
            int f = tid + i * 256;
            if (B_NK) {
                int n = f >> 2, kq = (f & 3) << 2;
                float v[4] = {pb[i].x, pb[i].y, pb[i].z, pb[i].w};
                #pragma unroll
                for (int j = 0; j < 4; j++)
                    Bs[(kq + j) * 128 + (n ^ (j << 3))] = f2tf(v[j]);
            } else {
                int k = f >> 5, n4 = (f & 31) << 2;
                uint32_t* p = &Bs[k * 128 + (n4 ^ ((k & 3) << 3))];
                p[0] = f2tf(pb[i].x); p[1] = f2tf(pb[i].y);
                p[2] = f2tf(pb[i].z); p[3] = f2tf(pb[i].w);
            }
        }
    };

    auto compute = [&](int k0) {
        const int kb = k0 * 128;
        uint32_t a[2][4], b[8][2];
        #pragma unroll
        for (int mt = 0; mt < 2; mt++) {
            a[mt][0] = As[kb + aoff[mt][0]];
            a[mt][1] = As[kb + aoff[mt][1]];
            a[mt][2] = As[kb + 512 + aoff[mt][0]];
            a[mt][3] = As[kb + 512 + aoff[mt][1]];
        }
        #pragma unroll
        for (int nt = 0; nt < 8; nt++) {
            b[nt][0] = Bs[kb + boff[nt]];
            b[nt][1] = Bs[kb + 512 + boff[nt]];
        }
        #pragma unroll
        for (int mt = 0; mt < 2; mt++)
            #pragma unroll
            for (int nt = 0; nt < 8; nt++)
                mma_tf32(acc[mt][nt], a[mt], b[nt]);
    };

    // Prologue
    loadA(0); loadB(0);
    storeA(); storeB();
    __syncthreads();

    for (int kt = 0; kt < K; kt += 16) {
        const bool more = (kt + 16) < K;
        if (more) { loadA(kt + 16); loadB(kt + 16); }
        compute(0);
        compute(8);
        __syncthreads();
        if (more) {
            storeA(); storeB();
            __syncthreads();
        }
    }

    // Epilogue: alpha scale + optional bias, float2 stores
    #pragma unroll
    for (int mt = 0; mt < 2; mt++) {
        const int rm = m0 + m0w + mt * 16 + g;
        const float bv0 = HAS_BIAS ? bias[rm]     : 0.0f;
        const float bv1 = HAS_BIAS ? bias[rm + 8] : 0.0f;
        #pragma unroll
        for (int nt = 0; nt < 8; nt++) {
            const int cn = n0 + n0w + nt * 8 + t * 2;
            float2 v0, v1;
            v0.x = alpha * acc[mt][nt][0] + bv0;
            v0.y = alpha * acc[mt][nt][1] + bv0;
            v1.x = alpha * acc[mt][nt][2] + bv1;
            v1.y = alpha * acc[mt][nt][3] + bv1;
            *reinterpret_cast<float2*>(&C[(size_t)rm * ldc + cn]) = v0;
            *reinterpret_cast<float2*>(&C[(size_t)(rm + 8) * ldc + cn]) = v1;
        }
    }
}

// ---------------------------------------------------------------------------
// In-place masked softmax over rows of length SEQL (=1024).
// ---------------------------------------------------------------------------
__global__ __launch_bounds__(256) void softmax_rows(
    float* __restrict__ S, const unsigned char* __restrict__ mask)
{
    const size_t row = blockIdx.x;
    float4* p = reinterpret_cast<float4*>(S + row * SEQL);
    const uchar4* mp = reinterpret_cast<const uchar4*>(mask + row * SEQL);
    const int t = threadIdx.x;

    float4 v = p[t];
    uchar4 m = mp[t];
    if (m.x) v.x = -1e9f;
    if (m.y) v.y = -1e9f;
    if (m.z) v.z = -1e9f;
    if (m.w) v.w = -1e9f;

    float mx = fmaxf(fmaxf(v.x, v.y), fmaxf(v.z, v.w));
    #pragma unroll
    for (int o = 16; o; o >>= 1) mx = fmaxf(mx, __shfl_xor_sync(0xffffffffu, mx, o));
    __shared__ float sm[8];
    const int w = t >> 5;
    if ((t & 31) == 0) sm[w] = mx;
    __syncthreads();
    float rmax = sm[0];
    #pragma unroll
    for (int i = 1; i < 8; i++) rmax = fmaxf(rmax, sm[i]);

    v.x = __expf(v.x - rmax);
    v.y = __expf(v.y - rmax);
    v.z = __expf(v.z - rmax);
    v.w = __expf(v.w - rmax);

    float s = v.x + v.y + v.z + v.w;
    #pragma unroll
    for (int o = 16; o; o >>= 1) s += __shfl_xor_sync(0xffffffffu, s, o);
    __shared__ float ss[8];
    if ((t & 31) == 0) ss[w] = s;
    __syncthreads();
    float tot = 0.0f;
    #pragma unroll
    for (int i = 0; i < 8; i++) tot += ss[i];

    float inv = 1.0f / tot;
    v.x *= inv; v.y *= inv; v.z *= inv; v.w *= inv;
    p[t] = v;
}

// ---------------------------------------------------------------------------
extern "C" void kernel_launch(void* const* d_in, const int* in_sizes, int n_in,
                              void* d_out, int out_size)
{
    const float* x        = (const float*)d_in[0];  // (8,512,32,32)
    const float* content  = (const float*)d_in[1];  // (8,1024,1024)
    const unsigned char* pmask = (const unsigned char*)d_in[2]; // (8,1024,1024)
    const float* W_in     = (const float*)d_in[3];  // (1024,512)
    const float* b_in     = (const float*)d_in[4];  // (1024,)
    const float* Wq       = (const float*)d_in[5];  // (1024,1024)
    const float* Wk       = (const float*)d_in[6];
    const float* Wv       = (const float*)d_in[7];
    const float* W_out    = (const float*)d_in[8];  // (512,1024)
    const float* b_out    = (const float*)d_in[9];  // (512,)

    float* out = (float*)d_out;                          // (8,512,32,32)
    float* att = out + (size_t)BATCH * CIND * NTOK;      // (8,1024,1024)

    float *XT, *Q, *Kp, *Vp;
    cudaGetSymbolAddress((void**)&XT, g_XT);
    cudaGetSymbolAddress((void**)&Q,  g_Q);
    cudaGetSymbolAddress((void**)&Kp, g_K);
    cudaGetSymbolAddress((void**)&Vp, g_V);

    const float scale = 1.0f / 32.0f;  // EMB^-0.5 with EMB=1024
    const size_t EN = (size_t)EMBD * NTOK;
    const size_t SE = (size_t)SEQL * EMBD;
    const size_t NS = (size_t)NTOK * SEQL;

    // 1. XT[e,n] = sum_c W_in[e,c] * x[b,c,n] + b_in[e]   (A: MK, B: KN)
    mm_tf32<false, false, true><<<dim3(NTOK/128, EMBD/128, BATCH), 256>>>(
        W_in, x, XT, b_in, CIND, CIND, NTOK, NTOK,
        0, (size_t)CIND * NTOK, EN, 1.0f);

    // 2. Q[e,n] = Wq @ XT    (A: MK, B: KN)
    mm_tf32<false, false, false><<<dim3(NTOK/128, EMBD/128, BATCH), 256>>>(
        Wq, XT, Q, nullptr, EMBD, EMBD, NTOK, NTOK,
        0, EN, EN, 1.0f);

    // 3. K[e,s] = Wk @ content^T   (A: MK, B: NK)
    mm_tf32<false, true, false><<<dim3(SEQL/128, EMBD/128, BATCH), 256>>>(
        Wk, content, Kp, nullptr, EMBD, EMBD, EMBD, SEQL,
        0, SE, SE, 1.0f);

    // 4. V[e,s]
    mm_tf32<false, true, false><<<dim3(SEQL/128, EMBD/128, BATCH), 256>>>(
        Wv, content, Vp, nullptr, EMBD, EMBD, EMBD, SEQL,
        0, SE, SE, 1.0f);

    // 5. S[i,j] = scale * Q^T @ K  -> att region   (A: KM, B: KN)
    mm_tf32<true, false, false><<<dim3(SEQL/128, NTOK/128, BATCH), 256>>>(
        Q, Kp, att, nullptr, EMBD, NTOK, SEQL, SEQL,
        EN, SE, NS, scale);

    // 6. masked softmax in place on att
    softmax_rows<<<BATCH * NTOK, 256>>>(att, pmask);

    // 7. O[d,i] = V @ att^T   (A: MK, B: NK)  (reuse XT scratch)
    mm_tf32<false, true, false><<<dim3(NTOK/128, EMBD/128, BATCH), 256>>>(
        Vp, att, XT, nullptr, SEQL, SEQL, SEQL, NTOK,
        SE, NS, EN, 1.0f);

    // 8. out[c,n] = W_out @ O + b_out   (A: MK, B: KN)
    mm_tf32<false, false, true><<<dim3(NTOK/128, CIND/128, BATCH), 256>>>(
        W_out, XT, out, b_out, EMBD, EMBD, NTOK, NTOK,
        0, EN, (size_t)CIND * NTOK, 1.0f);
}

// round 4
// speedup vs baseline: 3.5003x; 1.5418x over previous
#include <cuda_runtime.h>
#include <cstdint>

#define BATCH 8
#define EMBD  1024
#define CIND  512
#define NTOK  1024
#define SEQL  1024

// ---------------- scratch (device globals; allocation-free) ----------------
__device__ float g_xT[(size_t)BATCH * NTOK * CIND];   // x transposed: [b][n][c]
__device__ float g_XT[(size_t)BATCH * NTOK * EMBD];   // proj_in tokens [b][n][e]
__device__ float g_Q [(size_t)BATCH * NTOK * EMBD];   // [b][n][e]
__device__ float g_K [(size_t)BATCH * SEQL * EMBD];   // [b][s][e]
__device__ float g_V [(size_t)BATCH * EMBD * SEQL];   // V^T: [b][d][s]
__device__ float g_O [(size_t)BATCH * NTOK * EMBD];   // attention out [b][n][e]

// ---------------- helpers ----------------
__device__ __forceinline__ uint32_t smem_u32(const void* p) {
    uint32_t a;
    asm("{ .reg .u64 t; cvta.to.shared.u64 t, %1; cvt.u32.u64 %0, t; }" : "=r"(a) : "l"(p));
    return a;
}
__device__ __forceinline__ uint32_t f2tf(float x) {
    uint32_t r; asm("cvt.rna.tf32.f32 %0, %1;" : "=r"(r) : "f"(x)); return r;
}
#define CP_ASYNC16(dst, src) \
    asm volatile("cp.async.cg.shared.global.L2::128B [%0], [%1], 16;" \
                 :: "r"(dst), "l"(src) : "memory")
#define CP_COMMIT() asm volatile("cp.async.commit_group;" ::: "memory")
#define CP_WAIT1()  asm volatile("cp.async.wait_group 1;" ::: "memory")

__device__ __forceinline__ void mma_tf32(float* d, const uint32_t* a, const uint32_t* b) {
    asm volatile(
        "mma.sync.aligned.m16n8k8.row.col.f32.tf32.tf32.f32 "
        "{%0,%1,%2,%3}, {%4,%5,%6,%7}, {%8,%9}, {%0,%1,%2,%3};"
        : "+f"(d[0]), "+f"(d[1]), "+f"(d[2]), "+f"(d[3])
        : "r"(a[0]), "r"(a[1]), "r"(a[2]), "r"(a[3]), "r"(b[0]), "r"(b[1]));
}

// ---------------------------------------------------------------------------
// TF32 tensor-core GEMM:  C[m][n] = alpha * sum_k A[m][k] * B[n][k] (+bias)
// Both A and B K-major with row stride == K.
// Block tile 128x128, BK=32, 3-stage cp.async pipeline, 256 threads
// (8 warps as 4x2, warp tile 32x64). Raw fp32 in smem with 16B XOR swizzle;
// cvt to tf32 after fragment load (numerics identical to converting at store).
// MBIAS: 0 = none, 1 = row bias (per m), 2 = col bias (per n)
// ---------------------------------------------------------------------------
#define STAGE_BYTES 32768            // A 16KB + B 16KB
#define SMEM_BYTES  (3 * STAGE_BYTES)

template<int MBIAS>
__global__ __launch_bounds__(256, 2) void tc_gemm(
    const float* __restrict__ A, const float* __restrict__ B,
    float* __restrict__ C, const float* __restrict__ bias,
    int K, int ldc, size_t sA, size_t sB, size_t sC, float alpha)
{
    extern __shared__ char smem[];
    const uint32_t sbase = smem_u32(smem);
    const int tid  = threadIdx.x;
    const int wid  = tid >> 5, lane = tid & 31;
    const int g = lane >> 2, t = lane & 3;
    const int m0w = (wid & 3) * 32;
    const int n0w = (wid >> 2) * 64;

    const float* Ab = A + blockIdx.z * sA + (size_t)(blockIdx.y * 128) * K;
    const float* Bb = B + blockIdx.z * sB + (size_t)(blockIdx.x * 128) * K;
    float*       Cb = C + blockIdx.z * sC + (size_t)(blockIdx.y * 128) * ldc
                        + blockIdx.x * 128;

    // per-thread fill assignment: 4 chunks of A, 4 of B per stage
    const int fr = tid >> 3;          // base row (0..31), +32*i
    const int fq = tid & 7;           // 16B chunk in row

    auto issue = [&](int stage) {
        const uint32_t sa = sbase + (stage % 3) * STAGE_BYTES;
        const int k0 = stage * 32;
        #pragma unroll
        for (int i = 0; i < 4; i++) {
            const int r = fr + i * 32;
            const uint32_t dst = sa + r * 128 + ((fq ^ (r & 7)) << 4);
            CP_ASYNC16(dst, Ab + (size_t)r * K + k0 + fq * 4);
        }
        #pragma unroll
        for (int i = 0; i < 4; i++) {
            const int r = fr + i * 32;
            const uint32_t dst = sa + 16384 + r * 128 + ((fq ^ (r & 7)) << 4);
            CP_ASYNC16(dst, Bb + (size_t)r * K + k0 + fq * 4);
        }
    };

    float acc[2][8][4];
    #pragma unroll
    for (int mt = 0; mt < 2; mt++)
        #pragma unroll
        for (int nt = 0; nt < 8; nt++)
            #pragma unroll
            for (int i = 0; i < 4; i++) acc[mt][nt][i] = 0.0f;

    const int NC = K >> 5;

    issue(0); CP_COMMIT();
    issue(1); CP_COMMIT();

    for (int c = 0; c < NC; c++) {
        CP_WAIT1();
        __syncthreads();
        if (c + 2 < NC) issue(c + 2);
        CP_COMMIT();

        const float* As = reinterpret_cast<const float*>(smem + (c % 3) * STAGE_BYTES);
        const float* Bs = As + 4096;

        #pragma unroll
        for (int ks = 0; ks < 4; ks++) {
            const int sw0 = (ks * 8 + t)     ^ (g << 2);
            const int sw1 = (ks * 8 + t + 4) ^ (g << 2);
            uint32_t a[2][4], b[8][2];
            #pragma unroll
            for (int mt = 0; mt < 2; mt++) {
                const int r0 = (m0w + mt * 16 + g) * 32;
                a[mt][0] = f2tf(As[r0 + sw0]);
                a[mt][1] = f2tf(As[r0 + 256 + sw0]);   // row +8
                a[mt][2] = f2tf(As[r0 + sw1]);
                a[mt][3] = f2tf(As[r0 + 256 + sw1]);
            }
            #pragma unroll
            for (int nt = 0; nt < 8; nt++) {
                const int rn = (n0w + nt * 8 + g) * 32;
                b[nt][0] = f2tf(Bs[rn + sw0]);
                b[nt][1] = f2tf(Bs[rn + sw1]);
            }
            #pragma unroll
            for (int mt = 0; mt < 2; mt++)
                #pragma unroll
                for (int nt = 0; nt < 8; nt++)
                    mma_tf32(acc[mt][nt], a[mt], b[nt]);
        }
        __syncthreads();
    }

    // ---- epilogue ----
    #pragma unroll
    for (int mt = 0; mt < 2; mt++) {
        const int rm = blockIdx.y * 128 + m0w + mt * 16 + g;
        const float bv0 = (MBIAS == 1) ? __ldg(bias + rm)     : 0.0f;
        const float bv1 = (MBIAS == 1) ? __ldg(bias + rm + 8) : 0.0f;
        #pragma unroll
        for (int nt = 0; nt < 8; nt++) {
            const int cn = n0w + nt * 8 + t * 2;
            float cb0 = 0.0f, cb1 = 0.0f;
            if (MBIAS == 2) {
                cb0 = __ldg(bias + blockIdx.x * 128 + cn);
                cb1 = __ldg(bias + blockIdx.x * 128 + cn + 1);
            }
            float2 v0, v1;
            v0.x = alpha * acc[mt][nt][0] + bv0 + cb0;
            v0.y = alpha * acc[mt][nt][1] + bv0 + cb1;
            v1.x = alpha * acc[mt][nt][2] + bv1 + cb0;
            v1.y = alpha * acc[mt][nt][3] + bv1 + cb1;
            const int r = m0w + mt * 16 + g;
            *reinterpret_cast<float2*>(&Cb[(size_t)r * ldc + cn]) = v0;
            *reinterpret_cast<float2*>(&Cb[(size_t)(r + 8) * ldc + cn]) = v1;
        }
    }
}

// ---------------------------------------------------------------------------
// Transpose x: [b][512][1024] -> xT [b][1024][512]
// ---------------------------------------------------------------------------
__global__ void transpose_x(const float* __restrict__ in, float* __restrict__ out)
{
    __shared__ float tb[32][33];
    const int n0 = blockIdx.x * 32, c0 = blockIdx.y * 32;
    const float* ib = in  + (size_t)blockIdx.z * CIND * NTOK;
    float*       ob = out + (size_t)blockIdx.z * NTOK * CIND;
    const int tx = threadIdx.x, ty = threadIdx.y;
    #pragma unroll
    for (int j = 0; j < 32; j += 8)
        tb[ty + j][tx] = ib[(size_t)(c0 + ty + j) * NTOK + n0 + tx];
    __syncthreads();
    #pragma unroll
    for (int j = 0; j < 32; j += 8)
        ob[(size_t)(n0 + ty + j) * CIND + c0 + tx] = tb[tx][ty + j];
}

// ---------------------------------------------------------------------------
// In-place masked softmax over rows of length SEQL (=1024).
// ---------------------------------------------------------------------------
__global__ __launch_bounds__(256) void softmax_rows(
    float* __restrict__ S, const unsigned char* __restrict__ mask)
{
    const size_t row = blockIdx.x;
    float4* p = reinterpret_cast<float4*>(S + row * SEQL);
    const uchar4* mp = reinterpret_cast<const uchar4*>(mask + row * SEQL);
    const int t = threadIdx.x;

    float4 v = p[t];
    uchar4 m = mp[t];
    if (m.x) v.x = -1e9f;
    if (m.y) v.y = -1e9f;
    if (m.z) v.z = -1e9f;
    if (m.w) v.w = -1e9f;

    float mx = fmaxf(fmaxf(v.x, v.y), fmaxf(v.z, v.w));
    #pragma unroll
    for (int o = 16; o; o >>= 1) mx = fmaxf(mx, __shfl_xor_sync(0xffffffffu, mx, o));
    __shared__ float sm[8];
    const int w = t >> 5;
    if ((t & 31) == 0) sm[w] = mx;
    __syncthreads();
    float rmax = sm[0];
    #pragma unroll
    for (int i = 1; i < 8; i++) rmax = fmaxf(rmax, sm[i]);

    v.x = __expf(v.x - rmax); v.y = __expf(v.y - rmax);
    v.z = __expf(v.z - rmax); v.w = __expf(v.w - rmax);

    float s = v.x + v.y + v.z + v.w;
    #pragma unroll
    for (int o = 16; o; o >>= 1) s += __shfl_xor_sync(0xffffffffu, s, o);
    __shared__ float ss[8];
    if ((t & 31) == 0) ss[w] = s;
    __syncthreads();
    float tot = 0.0f;
    #pragma unroll
    for (int i = 0; i < 8; i++) tot += ss[i];

    float inv = 1.0f / tot;
    v.x *= inv; v.y *= inv; v.z *= inv; v.w *= inv;
    p[t] = v;
}

// ---------------------------------------------------------------------------
extern "C" void kernel_launch(void* const* d_in, const int* in_sizes, int n_in,
                              void* d_out, int out_size)
{
    const float* x       = (const float*)d_in[0];
    const float* content = (const float*)d_in[1];
    const unsigned char* pmask = (const unsigned char*)d_in[2];
    const float* W_in    = (const float*)d_in[3];
    const float* b_in    = (const float*)d_in[4];
    const float* Wq      = (const float*)d_in[5];
    const float* Wk      = (const float*)d_in[6];
    const float* Wv      = (const float*)d_in[7];
    const float* W_out   = (const float*)d_in[8];
    const float* b_out   = (const float*)d_in[9];

    float* out = (float*)d_out;                       // (8,512,32,32)
    float* att = out + (size_t)BATCH * CIND * NTOK;   // (8,1024,1024)

    float *xT, *XT, *Q, *Kp, *Vt, *O;
    cudaGetSymbolAddress((void**)&xT, g_xT);
    cudaGetSymbolAddress((void**)&XT, g_XT);
    cudaGetSymbolAddress((void**)&Q,  g_Q);
    cudaGetSymbolAddress((void**)&Kp, g_K);
    cudaGetSymbolAddress((void**)&Vt, g_V);
    cudaGetSymbolAddress((void**)&O,  g_O);

    cudaFuncSetAttribute(tc_gemm<0>, cudaFuncAttributeMaxDynamicSharedMemorySize, SMEM_BYTES);
    cudaFuncSetAttribute(tc_gemm<1>, cudaFuncAttributeMaxDynamicSharedMemorySize, SMEM_BYTES);
    cudaFuncSetAttribute(tc_gemm<2>, cudaFuncAttributeMaxDynamicSharedMemorySize, SMEM_BYTES);

    const size_t EN = (size_t)NTOK * EMBD;
    const size_t SE = (size_t)SEQL * EMBD;
    const size_t NS = (size_t)NTOK * SEQL;
    const size_t XC = (size_t)NTOK * CIND;
    const size_t CN = (size_t)CIND * NTOK;
    const float scale = 1.0f / 32.0f;

    // x -> xT  ([b][n][c])
    transpose_x<<<dim3(NTOK / 32, CIND / 32, BATCH), dim3(32, 8)>>>(x, xT);

    // 1. XT[n][e] = xT[n][c]·W_in[e][c] + b_in[e]   M=1024 N=1024 K=512, col bias
    tc_gemm<2><<<dim3(8, 8, BATCH), 256, SMEM_BYTES>>>(
        xT, W_in, XT, b_in, CIND, EMBD, XC, 0, EN, 1.0f);

    // 2. Q[n][e'] = XT[n][e]·Wq[e'][e]              K=1024
    tc_gemm<0><<<dim3(8, 8, BATCH), 256, SMEM_BYTES>>>(
        XT, Wq, Q, nullptr, EMBD, EMBD, EN, 0, EN, 1.0f);

    // 3. K[s][e'] = content[s][e]·Wk[e'][e]
    tc_gemm<0><<<dim3(8, 8, BATCH), 256, SMEM_BYTES>>>(
        content, Wk, Kp, nullptr, EMBD, EMBD, SE, 0, SE, 1.0f);

    // 4. Vt[d][s] = Wv[d][e]·content[s][e]
    tc_gemm<0><<<dim3(8, 8, BATCH), 256, SMEM_BYTES>>>(
        Wv, content, Vt, nullptr, EMBD, SEQL, 0, SE, SE, 1.0f);

    // 5. att[i][j] = scale * Q[i][e]·K[j][e]  -> att region of d_out
    tc_gemm<0><<<dim3(8, 8, BATCH), 256, SMEM_BYTES>>>(
        Q, Kp, att, nullptr, EMBD, SEQL, EN, SE, NS, scale);

    // 6. masked softmax in place
    softmax_rows<<<BATCH * NTOK, 256>>>(att, pmask);

    // 7. O[i][d] = att[i][j]·Vt[d][j]               K=1024
    tc_gemm<0><<<dim3(8, 8, BATCH), 256, SMEM_BYTES>>>(
        att, Vt, O, nullptr, SEQL, EMBD, NS, SE, EN, 1.0f);

    // 8. out[c][n] = W_out[c][e]·O[n][e] + b_out[c]  M=512 N=1024 K=1024, row bias
    tc_gemm<1><<<dim3(8, 4, BATCH), 256, SMEM_BYTES>>>(
        W_out, O, out, b_out, EMBD, NTOK, 0, EN, CN, 1.0f);
}

// round 5
// speedup vs baseline: 4.2249x; 1.2070x over previous
#include <cuda_runtime.h>
#include <cstdint>

#define BATCH 8
#define EMBD  1024
#define CIND  512
#define NTOK  1024
#define SEQL  1024

// ---------------- scratch (device globals; allocation-free) ----------------
__device__ float g_xT [(size_t)BATCH * NTOK * CIND];  // x^T, tf32-rounded
__device__ float g_XT [(size_t)BATCH * NTOK * EMBD];  // proj_in tokens (rounded)
__device__ float g_Q  [(size_t)BATCH * NTOK * EMBD];
__device__ float g_K  [(size_t)BATCH * SEQL * EMBD];
__device__ float g_V  [(size_t)BATCH * EMBD * SEQL];  // V^T (rounded)
__device__ float g_O  [(size_t)BATCH * NTOK * EMBD];
__device__ float g_aR [(size_t)BATCH * NTOK * SEQL];  // rounded copy of att
__device__ float g_Ct [(size_t)BATCH * SEQL * EMBD];  // rounded content
__device__ float g_Wi [EMBD * CIND];                  // rounded weights
__device__ float g_Wq2[EMBD * EMBD];
__device__ float g_Wk2[EMBD * EMBD];
__device__ float g_Wv2[EMBD * EMBD];
__device__ float g_Wo [CIND * EMBD];

// ---------------- helpers ----------------
__device__ __forceinline__ uint32_t smem_u32(const void* p) {
    uint32_t a;
    asm("{ .reg .u64 t; cvta.to.shared.u64 t, %1; cvt.u32.u64 %0, t; }" : "=r"(a) : "l"(p));
    return a;
}
__device__ __forceinline__ uint32_t f2tf(float x) {
    uint32_t r; asm("cvt.rna.tf32.f32 %0, %1;" : "=r"(r) : "f"(x)); return r;
}
__device__ __forceinline__ float rtf(float x) { return __uint_as_float(f2tf(x)); }

#define CP_ASYNC16(dst, src) \
    asm volatile("cp.async.cg.shared.global.L2::128B [%0], [%1], 16;" \
                 :: "r"(dst), "l"(src) : "memory")
#define CP_COMMIT() asm volatile("cp.async.commit_group;" ::: "memory")
#define CP_WAIT1()  asm volatile("cp.async.wait_group 1;" ::: "memory")

__device__ __forceinline__ void ldsm_x4(uint32_t* r, uint32_t a) {
    asm volatile("ldmatrix.sync.aligned.m8n8.x4.shared.b16 {%0,%1,%2,%3}, [%4];"
                 : "=r"(r[0]), "=r"(r[1]), "=r"(r[2]), "=r"(r[3]) : "r"(a));
}
__device__ __forceinline__ void ldsm_x2(uint32_t* r, uint32_t a) {
    asm volatile("ldmatrix.sync.aligned.m8n8.x2.shared.b16 {%0,%1}, [%2];"
                 : "=r"(r[0]), "=r"(r[1]) : "r"(a));
}
__device__ __forceinline__ void mma_tf32(float* d, const uint32_t* a, const uint32_t* b) {
    asm volatile(
        "mma.sync.aligned.m16n8k8.row.col.f32.tf32.tf32.f32 "
        "{%0,%1,%2,%3}, {%4,%5,%6,%7}, {%8,%9}, {%0,%1,%2,%3};"
        : "+f"(d[0]), "+f"(d[1]), "+f"(d[2]), "+f"(d[3])
        : "r"(a[0]), "r"(a[1]), "r"(a[2]), "r"(a[3]), "r"(b[0]), "r"(b[1]));
}

// ---------------------------------------------------------------------------
// TF32 tensor-core GEMM:  C[m][n] = alpha * sum_k A[m][k] * B[n][k] (+bias)
// A, B K-major, row stride == K, data PRE-ROUNDED to tf32 in memory.
// Block tile 128x128, BK=32, 3-stage cp.async pipeline, 256 threads
// (8 warps 4x2, warp tile 32x64). Fragments via ldmatrix.b16 (b32 words).
// MBIAS: 0 none, 1 row bias (per m), 2 col bias (per n). RND: round C store.
// ---------------------------------------------------------------------------
#define STAGE_BYTES 32768
#define SMEM_BYTES  (3 * STAGE_BYTES)

template<int MBIAS, int RND>
__global__ __launch_bounds__(256, 2) void tc_gemm(
    const float* __restrict__ A, const float* __restrict__ B,
    float* __restrict__ C, const float* __restrict__ bias,
    int K, int ldc, size_t sA, size_t sB, size_t sC, float alpha)
{
    extern __shared__ char smem[];
    const uint32_t sbase = smem_u32(smem);
    const int tid  = threadIdx.x;
    const int wid  = tid >> 5, lane = tid & 31;
    const int g = lane >> 2, t = lane & 3;
    const int m0w = (wid & 3) * 32;
    const int n0w = (wid >> 2) * 64;

    const float* Ab = A + blockIdx.z * sA + (size_t)(blockIdx.y * 128) * K;
    const float* Bb = B + blockIdx.z * sB + (size_t)(blockIdx.x * 128) * K;
    float*       Cb = C + blockIdx.z * sC + (size_t)(blockIdx.y * 128) * ldc
                        + blockIdx.x * 128;

    // cp.async fill assignment
    const int fr = tid >> 3;
    const int fq = tid & 7;

    auto issue = [&](int stage) {
        const uint32_t sa = sbase + (stage % 3) * STAGE_BYTES;
        const int k0 = stage * 32;
        #pragma unroll
        for (int i = 0; i < 4; i++) {
            const int r = fr + i * 32;
            const uint32_t dst = sa + r * 128 + ((fq ^ (r & 7)) << 4);
            CP_ASYNC16(dst, Ab + (size_t)r * K + k0 + fq * 4);
        }
        #pragma unroll
        for (int i = 0; i < 4; i++) {
            const int r = fr + i * 32;
            const uint32_t dst = sa + 16384 + r * 128 + ((fq ^ (r & 7)) << 4);
            CP_ASYNC16(dst, Bb + (size_t)r * K + k0 + fq * 4);
        }
    };

    // ldmatrix per-lane address precompute
    const int aRow8 = (lane & 7) + ((lane >> 3) & 1) * 8;   // row within 16-row tile
    const int aCSel = (lane >> 4) & 1;                      // 0: k-lo chunk, 1: k-hi
    uint32_t aBase[2]; int aPar[2];
    #pragma unroll
    for (int mt = 0; mt < 2; mt++) {
        const int r = m0w + mt * 16 + aRow8;
        aBase[mt] = (uint32_t)r * 128;
        aPar[mt]  = r & 7;
    }
    const int bCSel = (lane >> 3) & 1;
    uint32_t bBase[8]; int bPar[8];
    #pragma unroll
    for (int nt = 0; nt < 8; nt++) {
        const int r = n0w + nt * 8 + (lane & 7);
        bBase[nt] = 16384u + (uint32_t)r * 128;
        bPar[nt]  = r & 7;
    }

    float acc[2][8][4];
    #pragma unroll
    for (int mt = 0; mt < 2; mt++)
        #pragma unroll
        for (int nt = 0; nt < 8; nt++)
            #pragma unroll
            for (int i = 0; i < 4; i++) acc[mt][nt][i] = 0.0f;

    const int NC = K >> 5;
    issue(0); CP_COMMIT();
    issue(1); CP_COMMIT();

    for (int c = 0; c < NC; c++) {
        CP_WAIT1();
        __syncthreads();
        if (c + 2 < NC) issue(c + 2);
        CP_COMMIT();

        const uint32_t stg = sbase + (c % 3) * STAGE_BYTES;

        #pragma unroll
        for (int ks = 0; ks < 4; ks++) {
            const int ca = 2 * ks + aCSel;
            const int cb = 2 * ks + bCSel;
            uint32_t a[2][4], b[8][2];
            #pragma unroll
            for (int mt = 0; mt < 2; mt++)
                ldsm_x4(a[mt], stg + aBase[mt] + (uint32_t)((ca ^ aPar[mt]) << 4));
            #pragma unroll
            for (int nt = 0; nt < 8; nt++)
                ldsm_x2(b[nt], stg + bBase[nt] + (uint32_t)((cb ^ bPar[nt]) << 4));
            #pragma unroll
            for (int mt = 0; mt < 2; mt++)
                #pragma unroll
                for (int nt = 0; nt < 8; nt++)
                    mma_tf32(acc[mt][nt], a[mt], b[nt]);
        }
        __syncthreads();
    }

    // ---- epilogue ----
    #pragma unroll
    for (int mt = 0; mt < 2; mt++) {
        const int rm = blockIdx.y * 128 + m0w + mt * 16 + g;
        const float bv0 = (MBIAS == 1) ? __ldg(bias + rm)     : 0.0f;
        const float bv1 = (MBIAS == 1) ? __ldg(bias + rm + 8) : 0.0f;
        #pragma unroll
        for (int nt = 0; nt < 8; nt++) {
            const int cn = n0w + nt * 8 + t * 2;
            float cb0 = 0.0f, cb1 = 0.0f;
            if (MBIAS == 2) {
                cb0 = __ldg(bias + blockIdx.x * 128 + cn);
                cb1 = __ldg(bias + blockIdx.x * 128 + cn + 1);
            }
            float2 v0, v1;
            v0.x = alpha * acc[mt][nt][0] + bv0 + cb0;
            v0.y = alpha * acc[mt][nt][1] + bv0 + cb1;
            v1.x = alpha * acc[mt][nt][2] + bv1 + cb0;
            v1.y = alpha * acc[mt][nt][3] + bv1 + cb1;
            if (RND) {
                v0.x = rtf(v0.x); v0.y = rtf(v0.y);
                v1.x = rtf(v1.x); v1.y = rtf(v1.y);
            }
            const int r = m0w + mt * 16 + g;
            *reinterpret_cast<float2*>(&Cb[(size_t)r * ldc + cn]) = v0;
            *reinterpret_cast<float2*>(&Cb[(size_t)(r + 8) * ldc + cn]) = v1;
        }
    }
}

// ---------------------------------------------------------------------------
// Elementwise tf32 rounding copy (float4)
// ---------------------------------------------------------------------------
__global__ __launch_bounds__(256) void round_tf32(
    const float* __restrict__ in, float* __restrict__ out)
{
    const size_t i = (size_t)blockIdx.x * 256 + threadIdx.x;
    float4 v = reinterpret_cast<const float4*>(in)[i];
    v.x = rtf(v.x); v.y = rtf(v.y); v.z = rtf(v.z); v.w = rtf(v.w);
    reinterpret_cast<float4*>(out)[i] = v;
}

// ---------------------------------------------------------------------------
// Transpose x: [b][512][1024] -> xT [b][1024][512], tf32-rounded
// ---------------------------------------------------------------------------
__global__ void transpose_x(const float* __restrict__ in, float* __restrict__ out)
{
    __shared__ float tb[32][33];
    const int n0 = blockIdx.x * 32, c0 = blockIdx.y * 32;
    const float* ib = in  + (size_t)blockIdx.z * CIND * NTOK;
    float*       ob = out + (size_t)blockIdx.z * NTOK * CIND;
    const int tx = threadIdx.x, ty = threadIdx.y;
    #pragma unroll
    for (int j = 0; j < 32; j += 8)
        tb[ty + j][tx] = ib[(size_t)(c0 + ty + j) * NTOK + n0 + tx];
    __syncthreads();
    #pragma unroll
    for (int j = 0; j < 32; j += 8)
        ob[(size_t)(n0 + ty + j) * CIND + c0 + tx] = rtf(tb[tx][ty + j]);
}

// ---------------------------------------------------------------------------
// Masked softmax over rows of length SEQL. Writes exact att (in place) and a
// tf32-rounded copy for the P@V GEMM.
// ---------------------------------------------------------------------------
__global__ __launch_bounds__(256) void softmax_rows(
    float* __restrict__ S, float* __restrict__ SR,
    const unsigned char* __restrict__ mask)
{
    const size_t row = blockIdx.x;
    float4* p  = reinterpret_cast<float4*>(S  + row * SEQL);
    float4* pr = reinterpret_cast<float4*>(SR + row * SEQL);
    const uchar4* mp = reinterpret_cast<const uchar4*>(mask + row * SEQL);
    const int t = threadIdx.x;

    float4 v = p[t];
    uchar4 m = mp[t];
    if (m.x) v.x = -1e9f;
    if (m.y) v.y = -1e9f;
    if (m.z) v.z = -1e9f;
    if (m.w) v.w = -1e9f;

    float mx = fmaxf(fmaxf(v.x, v.y), fmaxf(v.z, v.w));
    #pragma unroll
    for (int o = 16; o; o >>= 1) mx = fmaxf(mx, __shfl_xor_sync(0xffffffffu, mx, o));
    __shared__ float sm[8];
    const int w = t >> 5;
    if ((t & 31) == 0) sm[w] = mx;
    __syncthreads();
    float rmax = sm[0];
    #pragma unroll
    for (int i = 1; i < 8; i++) rmax = fmaxf(rmax, sm[i]);

    v.x = __expf(v.x - rmax); v.y = __expf(v.y - rmax);
    v.z = __expf(v.z - rmax); v.w = __expf(v.w - rmax);

    float s = v.x + v.y + v.z + v.w;
    #pragma unroll
    for (int o = 16; o; o >>= 1) s += __shfl_xor_sync(0xffffffffu, s, o);
    __shared__ float ss[8];
    if ((t & 31) == 0) ss[w] = s;
    __syncthreads();
    float tot = 0.0f;
    #pragma unroll
    for (int i = 0; i < 8; i++) tot += ss[i];

    float inv = 1.0f / tot;
    v.x *= inv; v.y *= inv; v.z *= inv; v.w *= inv;
    p[t] = v;
    float4 r;
    r.x = rtf(v.x); r.y = rtf(v.y); r.z = rtf(v.z); r.w = rtf(v.w);
    pr[t] = r;
}

// ---------------------------------------------------------------------------
extern "C" void kernel_launch(void* const* d_in, const int* in_sizes, int n_in,
                              void* d_out, int out_size)
{
    const float* x       = (const float*)d_in[0];
    const float* content = (const float*)d_in[1];
    const unsigned char* pmask = (const unsigned char*)d_in[2];
    const float* W_in    = (const float*)d_in[3];
    const float* b_in    = (const float*)d_in[4];
    const float* Wq      = (const float*)d_in[5];
    const float* Wk      = (const float*)d_in[6];
    const float* Wv      = (const float*)d_in[7];
    const float* W_out   = (const float*)d_in[8];
    const float* b_out   = (const float*)d_in[9];

    float* out = (float*)d_out;                       // (8,512,32,32)
    float* att = out + (size_t)BATCH * CIND * NTOK;   // (8,1024,1024)

    float *xT, *XT, *Q, *Kp, *Vt, *O, *aR, *Ct, *Wi, *Wq2, *Wk2, *Wv2, *Wo;
    cudaGetSymbolAddress((void**)&xT,  g_xT);
    cudaGetSymbolAddress((void**)&XT,  g_XT);
    cudaGetSymbolAddress((void**)&Q,   g_Q);
    cudaGetSymbolAddress((void**)&Kp,  g_K);
    cudaGetSymbolAddress((void**)&Vt,  g_V);
    cudaGetSymbolAddress((void**)&O,   g_O);
    cudaGetSymbolAddress((void**)&aR,  g_aR);
    cudaGetSymbolAddress((void**)&Ct,  g_Ct);
    cudaGetSymbolAddress((void**)&Wi,  g_Wi);
    cudaGetSymbolAddress((void**)&Wq2, g_Wq2);
    cudaGetSymbolAddress((void**)&Wk2, g_Wk2);
    cudaGetSymbolAddress((void**)&Wv2, g_Wv2);
    cudaGetSymbolAddress((void**)&Wo,  g_Wo);

    cudaFuncSetAttribute(tc_gemm<0,0>, cudaFuncAttributeMaxDynamicSharedMemorySize, SMEM_BYTES);
    cudaFuncSetAttribute(tc_gemm<0,1>, cudaFuncAttributeMaxDynamicSharedMemorySize, SMEM_BYTES);
    cudaFuncSetAttribute(tc_gemm<1,0>, cudaFuncAttributeMaxDynamicSharedMemorySize, SMEM_BYTES);
    cudaFuncSetAttribute(tc_gemm<2,1>, cudaFuncAttributeMaxDynamicSharedMemorySize, SMEM_BYTES);

    const size_t EN = (size_t)NTOK * EMBD;
    const size_t SE = (size_t)SEQL * EMBD;
    const size_t NS = (size_t)NTOK * SEQL;
    const size_t XC = (size_t)NTOK * CIND;
    const size_t CN = (size_t)CIND * NTOK;
    const float scale = 1.0f / 32.0f;

    // ---- pre-round all external GEMM inputs to tf32 ----
    transpose_x<<<dim3(NTOK / 32, CIND / 32, BATCH), dim3(32, 8)>>>(x, xT);
    round_tf32<<<(BATCH * SE) / 1024, 256>>>(content, Ct);
    round_tf32<<<(EMBD * CIND) / 1024, 256>>>(W_in, Wi);
    round_tf32<<<(EMBD * EMBD) / 1024, 256>>>(Wq, Wq2);
    round_tf32<<<(EMBD * EMBD) / 1024, 256>>>(Wk, Wk2);
    round_tf32<<<(EMBD * EMBD) / 1024, 256>>>(Wv, Wv2);
    round_tf32<<<(CIND * EMBD) / 1024, 256>>>(W_out, Wo);

    // 1. XT[n][e] = xT[n][c]·Wi[e][c] + b_in[e]   (col bias, rounded out)
    tc_gemm<2,1><<<dim3(8, 8, BATCH), 256, SMEM_BYTES>>>(
        xT, Wi, XT, b_in, CIND, EMBD, XC, 0, EN, 1.0f);

    // 2. Q = XT·Wq^T (rounded out)
    tc_gemm<0,1><<<dim3(8, 8, BATCH), 256, SMEM_BYTES>>>(
        XT, Wq2, Q, nullptr, EMBD, EMBD, EN, 0, EN, 1.0f);

    // 3. K = content·Wk^T (rounded out)
    tc_gemm<0,1><<<dim3(8, 8, BATCH), 256, SMEM_BYTES>>>(
        Ct, Wk2, Kp, nullptr, EMBD, EMBD, SE, 0, SE, 1.0f);

    // 4. Vt[d][s] = Wv[d][e]·content[s][e] (rounded out)
    tc_gemm<0,1><<<dim3(8, 8, BATCH), 256, SMEM_BYTES>>>(
        Wv2, Ct, Vt, nullptr, EMBD, SEQL, 0, SE, SE, 1.0f);

    // 5. att = scale * Q·K^T  (exact out -> d_out att region)
    tc_gemm<0,0><<<dim3(8, 8, BATCH), 256, SMEM_BYTES>>>(
        Q, Kp, att, nullptr, EMBD, SEQL, EN, SE, NS, scale);

    // 6. masked softmax: att (exact) + aR (rounded)
    softmax_rows<<<BATCH * NTOK, 256>>>(att, aR, pmask);

    // 7. O[i][d] = aR[i][j]·Vt[d][j] (rounded out)
    tc_gemm<0,1><<<dim3(8, 8, BATCH), 256, SMEM_BYTES>>>(
        aR, Vt, O, nullptr, SEQL, EMBD, NS, SE, EN, 1.0f);

    // 8. out[c][n] = Wo[c][e]·O[n][e] + b_out[c]  (row bias, exact out)
    tc_gemm<1,0><<<dim3(8, 4, BATCH), 256, SMEM_BYTES>>>(
        Wo, O, out, b_out, EMBD, NTOK, 0, EN, CN, 1.0f);
}

// round 6
// speedup vs baseline: 4.6413x; 1.0986x over previous
#include <cuda_runtime.h>
#include <cstdint>

#define BATCH 8
#define EMBD  1024
#define CIND  512
#define NTOK  1024
#define SEQL  1024

// ---------------- scratch (device globals; allocation-free) ----------------
__device__ float g_xT [(size_t)BATCH * NTOK * CIND];  // x^T, tf32-rounded
__device__ float g_XT [(size_t)BATCH * NTOK * EMBD];  // proj_in tokens (rounded)
__device__ float g_Q  [(size_t)BATCH * NTOK * EMBD];
__device__ float g_K  [(size_t)BATCH * SEQL * EMBD];
__device__ float g_V  [(size_t)BATCH * EMBD * SEQL];  // V^T (rounded)
__device__ float g_O  [(size_t)BATCH * NTOK * EMBD];
__device__ float g_aR [(size_t)BATCH * NTOK * SEQL];  // rounded copy of att
__device__ float g_Ct [(size_t)BATCH * SEQL * EMBD];  // rounded content
__device__ float g_Wi [EMBD * CIND];                  // rounded weights
__device__ float g_Wq2[EMBD * EMBD];
__device__ float g_Wk2[EMBD * EMBD];
__device__ float g_Wv2[EMBD * EMBD];
__device__ float g_Wo [CIND * EMBD];

// ---------------- helpers ----------------
__device__ __forceinline__ uint32_t smem_u32(const void* p) {
    uint32_t a;
    asm("{ .reg .u64 t; cvta.to.shared.u64 t, %1; cvt.u32.u64 %0, t; }" : "=r"(a) : "l"(p));
    return a;
}
__device__ __forceinline__ uint32_t f2tf(float x) {
    uint32_t r; asm("cvt.rna.tf32.f32 %0, %1;" : "=r"(r) : "f"(x)); return r;
}
__device__ __forceinline__ float rtf(float x) { return __uint_as_float(f2tf(x)); }

#define CP_ASYNC16(dst, src) \
    asm volatile("cp.async.cg.shared.global.L2::128B [%0], [%1], 16;" \
                 :: "r"(dst), "l"(src) : "memory")
#define CP_COMMIT() asm volatile("cp.async.commit_group;" ::: "memory")
#define CP_WAIT1()  asm volatile("cp.async.wait_group 1;" ::: "memory")

__device__ __forceinline__ void ldsm_x4(uint32_t* r, uint32_t a) {
    asm volatile("ldmatrix.sync.aligned.m8n8.x4.shared.b16 {%0,%1,%2,%3}, [%4];"
                 : "=r"(r[0]), "=r"(r[1]), "=r"(r[2]), "=r"(r[3]) : "r"(a));
}
__device__ __forceinline__ void ldsm_x2(uint32_t* r, uint32_t a) {
    asm volatile("ldmatrix.sync.aligned.m8n8.x2.shared.b16 {%0,%1}, [%2];"
                 : "=r"(r[0]), "=r"(r[1]) : "r"(a));
}
__device__ __forceinline__ void mma_tf32(float* d, const uint32_t* a, const uint32_t* b) {
    asm volatile(
        "mma.sync.aligned.m16n8k8.row.col.f32.tf32.tf32.f32 "
        "{%0,%1,%2,%3}, {%4,%5,%6,%7}, {%8,%9}, {%0,%1,%2,%3};"
        : "+f"(d[0]), "+f"(d[1]), "+f"(d[2]), "+f"(d[3])
        : "r"(a[0]), "r"(a[1]), "r"(a[2]), "r"(a[3]), "r"(b[0]), "r"(b[1]));
}

// ---------------------------------------------------------------------------
// TF32 tensor-core GEMM:  C[m][n] = alpha * sum_k A[m][k] * B[n][k] (+bias)
// A, B K-major, row stride == K, data PRE-ROUNDED to tf32 in memory.
// Block tile 128x128, BK=32, 3-stage cp.async pipeline, 256 threads
// (8 warps 4x2, warp tile 32x64). Fragments via ldmatrix.b16 (b32 words).
// MBIAS: 0 none, 1 row bias (per m), 2 col bias (per n). RND: round C store.
// ---------------------------------------------------------------------------
#define STAGE_BYTES 32768
#define SMEM_BYTES  (3 * STAGE_BYTES)

template<int MBIAS, int RND>
__global__ __launch_bounds__(256, 2) void tc_gemm(
    const float* __restrict__ A, const float* __restrict__ B,
    float* __restrict__ C, const float* __restrict__ bias,
    int K, int ldc, size_t sA, size_t sB, size_t sC, float alpha)
{
    extern __shared__ char smem[];
    const uint32_t sbase = smem_u32(smem);
    const int tid  = threadIdx.x;
    const int wid  = tid >> 5, lane = tid & 31;
    const int g = lane >> 2, t = lane & 3;
    const int m0w = (wid & 3) * 32;
    const int n0w = (wid >> 2) * 64;

    const float* Ab = A + blockIdx.z * sA + (size_t)(blockIdx.y * 128) * K;
    const float* Bb = B + blockIdx.z * sB + (size_t)(blockIdx.x * 128) * K;
    float*       Cb = C + blockIdx.z * sC + (size_t)(blockIdx.y * 128) * ldc
                        + blockIdx.x * 128;

    const int fr = tid >> 3;
    const int fq = tid & 7;

    auto issue = [&](int stage) {
        const uint32_t sa = sbase + (stage % 3) * STAGE_BYTES;
        const int k0 = stage * 32;
        #pragma unroll
        for (int i = 0; i < 4; i++) {
            const int r = fr + i * 32;
            const uint32_t dst = sa + r * 128 + ((fq ^ (r & 7)) << 4);
            CP_ASYNC16(dst, Ab + (size_t)r * K + k0 + fq * 4);
        }
        #pragma unroll
        for (int i = 0; i < 4; i++) {
            const int r = fr + i * 32;
            const uint32_t dst = sa + 16384 + r * 128 + ((fq ^ (r & 7)) << 4);
            CP_ASYNC16(dst, Bb + (size_t)r * K + k0 + fq * 4);
        }
    };

    const int aRow8 = (lane & 7) + ((lane >> 3) & 1) * 8;
    const int aCSel = (lane >> 4) & 1;
    uint32_t aBase[2]; int aPar[2];
    #pragma unroll
    for (int mt = 0; mt < 2; mt++) {
        const int r = m0w + mt * 16 + aRow8;
        aBase[mt] = (uint32_t)r * 128;
        aPar[mt]  = r & 7;
    }
    const int bCSel = (lane >> 3) & 1;
    uint32_t bBase[8]; int bPar[8];
    #pragma unroll
    for (int nt = 0; nt < 8; nt++) {
        const int r = n0w + nt * 8 + (lane & 7);
        bBase[nt] = 16384u + (uint32_t)r * 128;
        bPar[nt]  = r & 7;
    }

    float acc[2][8][4];
    #pragma unroll
    for (int mt = 0; mt < 2; mt++)
        #pragma unroll
        for (int nt = 0; nt < 8; nt++)
            #pragma unroll
            for (int i = 0; i < 4; i++) acc[mt][nt][i] = 0.0f;

    const int NC = K >> 5;
    issue(0); CP_COMMIT();
    issue(1); CP_COMMIT();

    for (int c = 0; c < NC; c++) {
        CP_WAIT1();
        __syncthreads();
        if (c + 2 < NC) issue(c + 2);
        CP_COMMIT();

        const uint32_t stg = sbase + (c % 3) * STAGE_BYTES;

        #pragma unroll
        for (int ks = 0; ks < 4; ks++) {
            const int ca = 2 * ks + aCSel;
            const int cb = 2 * ks + bCSel;
            uint32_t a[2][4], b[8][2];
            #pragma unroll
            for (int mt = 0; mt < 2; mt++)
                ldsm_x4(a[mt], stg + aBase[mt] + (uint32_t)((ca ^ aPar[mt]) << 4));
            #pragma unroll
            for (int nt = 0; nt < 8; nt++)
                ldsm_x2(b[nt], stg + bBase[nt] + (uint32_t)((cb ^ bPar[nt]) << 4));
            #pragma unroll
            for (int mt = 0; mt < 2; mt++)
                #pragma unroll
                for (int nt = 0; nt < 8; nt++)
                    mma_tf32(acc[mt][nt], a[mt], b[nt]);
        }
        __syncthreads();
    }

    #pragma unroll
    for (int mt = 0; mt < 2; mt++) {
        const int rm = blockIdx.y * 128 + m0w + mt * 16 + g;
        const float bv0 = (MBIAS == 1) ? __ldg(bias + rm)     : 0.0f;
        const float bv1 = (MBIAS == 1) ? __ldg(bias + rm + 8) : 0.0f;
        #pragma unroll
        for (int nt = 0; nt < 8; nt++) {
            const int cn = n0w + nt * 8 + t * 2;
            float cb0 = 0.0f, cb1 = 0.0f;
            if (MBIAS == 2) {
                cb0 = __ldg(bias + blockIdx.x * 128 + cn);
                cb1 = __ldg(bias + blockIdx.x * 128 + cn + 1);
            }
            float2 v0, v1;
            v0.x = alpha * acc[mt][nt][0] + bv0 + cb0;
            v0.y = alpha * acc[mt][nt][1] + bv0 + cb1;
            v1.x = alpha * acc[mt][nt][2] + bv1 + cb0;
            v1.y = alpha * acc[mt][nt][3] + bv1 + cb1;
            if (RND) {
                v0.x = rtf(v0.x); v0.y = rtf(v0.y);
                v1.x = rtf(v1.x); v1.y = rtf(v1.y);
            }
            const int r = m0w + mt * 16 + g;
            *reinterpret_cast<float2*>(&Cb[(size_t)r * ldc + cn]) = v0;
            *reinterpret_cast<float2*>(&Cb[(size_t)(r + 8) * ldc + cn]) = v1;
        }
    }
}

// ---------------------------------------------------------------------------
__global__ __launch_bounds__(256) void round_tf32(
    const float* __restrict__ in, float* __restrict__ out)
{
    const size_t i = (size_t)blockIdx.x * 256 + threadIdx.x;
    float4 v = reinterpret_cast<const float4*>(in)[i];
    v.x = rtf(v.x); v.y = rtf(v.y); v.z = rtf(v.z); v.w = rtf(v.w);
    reinterpret_cast<float4*>(out)[i] = v;
}

// ---------------------------------------------------------------------------
__global__ void transpose_x(const float* __restrict__ in, float* __restrict__ out)
{
    __shared__ float tb[32][33];
    const int n0 = blockIdx.x * 32, c0 = blockIdx.y * 32;
    const float* ib = in  + (size_t)blockIdx.z * CIND * NTOK;
    float*       ob = out + (size_t)blockIdx.z * NTOK * CIND;
    const int tx = threadIdx.x, ty = threadIdx.y;
    #pragma unroll
    for (int j = 0; j < 32; j += 8)
        tb[ty + j][tx] = ib[(size_t)(c0 + ty + j) * NTOK + n0 + tx];
    __syncthreads();
    #pragma unroll
    for (int j = 0; j < 32; j += 8)
        ob[(size_t)(n0 + ty + j) * CIND + c0 + tx] = rtf(tb[tx][ty + j]);
}

// ---------------------------------------------------------------------------
__global__ __launch_bounds__(256) void softmax_rows(
    float* __restrict__ S, float* __restrict__ SR,
    const unsigned char* __restrict__ mask)
{
    const size_t row = blockIdx.x;
    float4* p  = reinterpret_cast<float4*>(S  + row * SEQL);
    float4* pr = reinterpret_cast<float4*>(SR + row * SEQL);
    const uchar4* mp = reinterpret_cast<const uchar4*>(mask + row * SEQL);
    const int t = threadIdx.x;

    float4 v = p[t];
    uchar4 m = mp[t];
    if (m.x) v.x = -1e9f;
    if (m.y) v.y = -1e9f;
    if (m.z) v.z = -1e9f;
    if (m.w) v.w = -1e9f;

    float mx = fmaxf(fmaxf(v.x, v.y), fmaxf(v.z, v.w));
    #pragma unroll
    for (int o = 16; o; o >>= 1) mx = fmaxf(mx, __shfl_xor_sync(0xffffffffu, mx, o));
    __shared__ float sm[8];
    const int w = t >> 5;
    if ((t & 31) == 0) sm[w] = mx;
    __syncthreads();
    float rmax = sm[0];
    #pragma unroll
    for (int i = 1; i < 8; i++) rmax = fmaxf(rmax, sm[i]);

    v.x = __expf(v.x - rmax); v.y = __expf(v.y - rmax);
    v.z = __expf(v.z - rmax); v.w = __expf(v.w - rmax);

    float s = v.x + v.y + v.z + v.w;
    #pragma unroll
    for (int o = 16; o; o >>= 1) s += __shfl_xor_sync(0xffffffffu, s, o);
    __shared__ float ss[8];
    if ((t & 31) == 0) ss[w] = s;
    __syncthreads();
    float tot = 0.0f;
    #pragma unroll
    for (int i = 0; i < 8; i++) tot += ss[i];

    float inv = 1.0f / tot;
    v.x *= inv; v.y *= inv; v.z *= inv; v.w *= inv;
    p[t] = v;
    float4 r;
    r.x = rtf(v.x); r.y = rtf(v.y); r.z = rtf(v.z); r.w = rtf(v.w);
    pr[t] = r;
}

// ---------------------------------------------------------------------------
extern "C" void kernel_launch(void* const* d_in, const int* in_sizes, int n_in,
                              void* d_out, int out_size)
{
    const float* x       = (const float*)d_in[0];
    const float* content = (const float*)d_in[1];
    const unsigned char* pmask = (const unsigned char*)d_in[2];
    const float* W_in    = (const float*)d_in[3];
    const float* b_in    = (const float*)d_in[4];
    const float* Wq      = (const float*)d_in[5];
    const float* Wk      = (const float*)d_in[6];
    const float* Wv      = (const float*)d_in[7];
    const float* W_out   = (const float*)d_in[8];
    const float* b_out   = (const float*)d_in[9];

    float* out = (float*)d_out;                       // (8,512,32,32)
    float* att = out + (size_t)BATCH * CIND * NTOK;   // (8,1024,1024)

    float *xT, *XT, *Q, *Kp, *Vt, *O, *aR, *Ct, *Wi, *Wq2, *Wk2, *Wv2, *Wo;
    cudaGetSymbolAddress((void**)&xT,  g_xT);
    cudaGetSymbolAddress((void**)&XT,  g_XT);
    cudaGetSymbolAddress((void**)&Q,   g_Q);
    cudaGetSymbolAddress((void**)&Kp,  g_K);
    cudaGetSymbolAddress((void**)&Vt,  g_V);
    cudaGetSymbolAddress((void**)&O,   g_O);
    cudaGetSymbolAddress((void**)&aR,  g_aR);
    cudaGetSymbolAddress((void**)&Ct,  g_Ct);
    cudaGetSymbolAddress((void**)&Wi,  g_Wi);
    cudaGetSymbolAddress((void**)&Wq2, g_Wq2);
    cudaGetSymbolAddress((void**)&Wk2, g_Wk2);
    cudaGetSymbolAddress((void**)&Wv2, g_Wv2);
    cudaGetSymbolAddress((void**)&Wo,  g_Wo);

    cudaFuncSetAttribute(tc_gemm<0,0>, cudaFuncAttributeMaxDynamicSharedMemorySize, SMEM_BYTES);
    cudaFuncSetAttribute(tc_gemm<0,1>, cudaFuncAttributeMaxDynamicSharedMemorySize, SMEM_BYTES);
    cudaFuncSetAttribute(tc_gemm<1,0>, cudaFuncAttributeMaxDynamicSharedMemorySize, SMEM_BYTES);
    cudaFuncSetAttribute(tc_gemm<2,1>, cudaFuncAttributeMaxDynamicSharedMemorySize, SMEM_BYTES);

    // One-time creation of side stream + events (first call is the uncaptured
    // correctness run; captured calls only record/wait, which is legal and
    // produces the identical graph every time).
    static cudaStream_t s1 = nullptr;
    static cudaEvent_t eF = nullptr, eK = nullptr, eV = nullptr;
    if (s1 == nullptr) {
        cudaStreamCreateWithFlags(&s1, cudaStreamNonBlocking);
        cudaEventCreateWithFlags(&eF, cudaEventDisableTiming);
        cudaEventCreateWithFlags(&eK, cudaEventDisableTiming);
        cudaEventCreateWithFlags(&eV, cudaEventDisableTiming);
    }

    const size_t EN = (size_t)NTOK * EMBD;
    const size_t SE = (size_t)SEQL * EMBD;
    const size_t NS = (size_t)NTOK * SEQL;
    const size_t XC = (size_t)NTOK * CIND;
    const size_t CN = (size_t)CIND * NTOK;
    const float scale = 1.0f / 32.0f;

    // ---- fork side stream ----
    cudaEventRecord(eF, 0);
    cudaStreamWaitEvent(s1, eF, 0);

    // ---- s1: content/K/V chain ----
    round_tf32<<<(BATCH * SE) / 1024, 256, 0, s1>>>(content, Ct);
    round_tf32<<<(EMBD * EMBD) / 1024, 256, 0, s1>>>(Wk, Wk2);
    // K = content·Wk^T (rounded out)
    tc_gemm<0,1><<<dim3(8, 8, BATCH), 256, SMEM_BYTES, s1>>>(
        Ct, Wk2, Kp, nullptr, EMBD, EMBD, SE, 0, SE, 1.0f);
    cudaEventRecord(eK, s1);
    round_tf32<<<(EMBD * EMBD) / 1024, 256, 0, s1>>>(Wv, Wv2);
    // Vt[d][s] = Wv[d][e]·content[s][e] (rounded out)
    tc_gemm<0,1><<<dim3(8, 8, BATCH), 256, SMEM_BYTES, s1>>>(
        Wv2, Ct, Vt, nullptr, EMBD, SEQL, 0, SE, SE, 1.0f);
    round_tf32<<<(CIND * EMBD) / 1024, 256, 0, s1>>>(W_out, Wo);
    cudaEventRecord(eV, s1);

    // ---- s0 (default): x/Q chain ----
    transpose_x<<<dim3(NTOK / 32, CIND / 32, BATCH), dim3(32, 8)>>>(x, xT);
    round_tf32<<<(EMBD * CIND) / 1024, 256>>>(W_in, Wi);
    // XT[n][e] = xT[n][c]·Wi[e][c] + b_in[e]   (col bias, rounded out)
    tc_gemm<2,1><<<dim3(8, 8, BATCH), 256, SMEM_BYTES>>>(
        xT, Wi, XT, b_in, CIND, EMBD, XC, 0, EN, 1.0f);
    round_tf32<<<(EMBD * EMBD) / 1024, 256>>>(Wq, Wq2);
    // Q = XT·Wq^T (rounded out)
    tc_gemm<0,1><<<dim3(8, 8, BATCH), 256, SMEM_BYTES>>>(
        XT, Wq2, Q, nullptr, EMBD, EMBD, EN, 0, EN, 1.0f);

    // ---- join for scores (needs K); V still running on s1 ----
    cudaStreamWaitEvent(0, eK, 0);
    // att = scale * Q·K^T  (exact out -> d_out att region)
    tc_gemm<0,0><<<dim3(8, 8, BATCH), 256, SMEM_BYTES>>>(
        Q, Kp, att, nullptr, EMBD, SEQL, EN, SE, NS, scale);

    // masked softmax: att (exact) + aR (rounded)
    softmax_rows<<<BATCH * NTOK, 256>>>(att, aR, pmask);

    // ---- join for P@V (needs Vt and Wo ready) ----
    cudaStreamWaitEvent(0, eV, 0);
    // O[i][d] = aR[i][j]·Vt[d][j] (rounded out)
    tc_gemm<0,1><<<dim3(8, 8, BATCH), 256, SMEM_BYTES>>>(
        aR, Vt, O, nullptr, SEQL, EMBD, NS, SE, EN, 1.0f);

    // out[c][n] = Wo[c][e]·O[n][e] + b_out[c]  (row bias, exact out)
    tc_gemm<1,0><<<dim3(8, 4, BATCH), 256, SMEM_BYTES>>>(
        Wo, O, out, b_out, EMBD, NTOK, 0, EN, CN, 1.0f);
}

// round 8
// speedup vs baseline: 6.9478x; 1.4970x over previous
#include <cuda_runtime.h>
#include <cstdint>

#define BATCH 8
#define EMBD  1024
#define CIND  512
#define NTOK  1024
#define SEQL  1024

// ---------------- scratch (device globals; allocation-free) ----------------
__device__ float g_xT [(size_t)BATCH * NTOK * CIND];  // x^T, tf32-rounded
__device__ float g_Q  [(size_t)BATCH * NTOK * EMBD];
__device__ float g_K  [(size_t)BATCH * SEQL * EMBD];
__device__ float g_Ct [(size_t)BATCH * SEQL * EMBD];  // rounded content
__device__ float g_aR [(size_t)BATCH * NTOK * SEQL];  // rounded copy of att
__device__ float g_Ut [(size_t)BATCH * CIND * SEQL];  // Ut[c][s]
__device__ float g_Wq2[EMBD * EMBD];                  // rounded Wq
__device__ float g_Wk2[EMBD * EMBD];                  // rounded Wk
__device__ float g_Wit[CIND * EMBD];                  // W_in^T rounded
__device__ float g_Wqi[EMBD * CIND];                  // folded Wq·W_in
__device__ float g_bq [EMBD];                         // folded Wq·b_in
__device__ float g_Wo2[CIND * EMBD];                  // rounded W_out
__device__ float g_Wvt[EMBD * EMBD];                  // Wv^T rounded
__device__ float g_Wvo[CIND * EMBD];                  // folded W_out·Wv

// ---------------- helpers ----------------
__device__ __forceinline__ uint32_t smem_u32(const void* p) {
    uint32_t a;
    asm("{ .reg .u64 t; cvta.to.shared.u64 t, %1; cvt.u32.u64 %0, t; }" : "=r"(a) : "l"(p));
    return a;
}
__device__ __forceinline__ uint32_t f2tf(float x) {
    uint32_t r; asm("cvt.rna.tf32.f32 %0, %1;" : "=r"(r) : "f"(x)); return r;
}
__device__ __forceinline__ float rtf(float x) { return __uint_as_float(f2tf(x)); }

#define CP_ASYNC16(dst, src) \
    asm volatile("cp.async.cg.shared.global.L2::128B [%0], [%1], 16;" \
                 :: "r"(dst), "l"(src) : "memory")
#define CP_COMMIT() asm volatile("cp.async.commit_group;" ::: "memory")
#define CP_WAIT1()  asm volatile("cp.async.wait_group 1;" ::: "memory")

__device__ __forceinline__ void ldsm_x4(uint32_t* r, uint32_t a) {
    asm volatile("ldmatrix.sync.aligned.m8n8.x4.shared.b16 {%0,%1,%2,%3}, [%4];"
                 : "=r"(r[0]), "=r"(r[1]), "=r"(r[2]), "=r"(r[3]) : "r"(a));
}
__device__ __forceinline__ void ldsm_x2(uint32_t* r, uint32_t a) {
    asm volatile("ldmatrix.sync.aligned.m8n8.x2.shared.b16 {%0,%1}, [%2];"
                 : "=r"(r[0]), "=r"(r[1]) : "r"(a));
}
__device__ __forceinline__ void mma_tf32(float* d, const uint32_t* a, const uint32_t* b) {
    asm volatile(
        "mma.sync.aligned.m16n8k8.row.col.f32.tf32.tf32.f32 "
        "{%0,%1,%2,%3}, {%4,%5,%6,%7}, {%8,%9}, {%0,%1,%2,%3};"
        : "+f"(d[0]), "+f"(d[1]), "+f"(d[2]), "+f"(d[3])
        : "r"(a[0]), "r"(a[1]), "r"(a[2]), "r"(a[3]), "r"(b[0]), "r"(b[1]));
}

// ---------------------------------------------------------------------------
// TF32 tensor-core GEMM:  C[m][n] = alpha * sum_k A[m][k] * B[n][k] (+bias)
// A, B K-major, row stride == K, data PRE-ROUNDED to tf32 in memory.
// Block tile 128x128, BK=32, 3-stage cp.async pipeline, 256 threads.
// MBIAS: 0 none, 1 row bias (per m), 2 col bias (per n). RND: round C store.
// ---------------------------------------------------------------------------
#define STAGE_BYTES 32768
#define SMEM_BYTES  (3 * STAGE_BYTES)

template<int MBIAS, int RND>
__global__ __launch_bounds__(256, 2) void tc_gemm(
    const float* __restrict__ A, const float* __restrict__ B,
    float* __restrict__ C, const float* __restrict__ bias,
    int K, int ldc, size_t sA, size_t sB, size_t sC, float alpha)
{
    extern __shared__ char smem[];
    const uint32_t sbase = smem_u32(smem);
    const int tid  = threadIdx.x;
    const int wid  = tid >> 5, lane = tid & 31;
    const int g = lane >> 2, t = lane & 3;
    const int m0w = (wid & 3) * 32;
    const int n0w = (wid >> 2) * 64;

    const float* Ab = A + blockIdx.z * sA + (size_t)(blockIdx.y * 128) * K;
    const float* Bb = B + blockIdx.z * sB + (size_t)(blockIdx.x * 128) * K;
    float*       Cb = C + blockIdx.z * sC + (size_t)(blockIdx.y * 128) * ldc
                        + blockIdx.x * 128;

    const int fr = tid >> 3;
    const int fq = tid & 7;

    auto issue = [&](int stage) {
        const uint32_t sa = sbase + (stage % 3) * STAGE_BYTES;
        const int k0 = stage * 32;
        #pragma unroll
        for (int i = 0; i < 4; i++) {
            const int r = fr + i * 32;
            const uint32_t dst = sa + r * 128 + ((fq ^ (r & 7)) << 4);
            CP_ASYNC16(dst, Ab + (size_t)r * K + k0 + fq * 4);
        }
        #pragma unroll
        for (int i = 0; i < 4; i++) {
            const int r = fr + i * 32;
            const uint32_t dst = sa + 16384 + r * 128 + ((fq ^ (r & 7)) << 4);
            CP_ASYNC16(dst, Bb + (size_t)r * K + k0 + fq * 4);
        }
    };

    const int aRow8 = (lane & 7) + ((lane >> 3) & 1) * 8;
    const int aCSel = (lane >> 4) & 1;
    uint32_t aBase[2]; int aPar[2];
    #pragma unroll
    for (int mt = 0; mt < 2; mt++) {
        const int r = m0w + mt * 16 + aRow8;
        aBase[mt] = (uint32_t)r * 128;
        aPar[mt]  = r & 7;
    }
    const int bCSel = (lane >> 3) & 1;
    uint32_t bBase[8]; int bPar[8];
    #pragma unroll
    for (int nt = 0; nt < 8; nt++) {
        const int r = n0w + nt * 8 + (lane & 7);
        bBase[nt] = 16384u + (uint32_t)r * 128;
        bPar[nt]  = r & 7;
    }

    float acc[2][8][4];
    #pragma unroll
    for (int mt = 0; mt < 2; mt++)
        #pragma unroll
        for (int nt = 0; nt < 8; nt++)
            #pragma unroll
            for (int i = 0; i < 4; i++) acc[mt][nt][i] = 0.0f;

    const int NC = K >> 5;
    issue(0); CP_COMMIT();
    issue(1); CP_COMMIT();

    for (int c = 0; c < NC; c++) {
        CP_WAIT1();
        __syncthreads();
        if (c + 2 < NC) issue(c + 2);
        CP_COMMIT();

        const uint32_t stg = sbase + (c % 3) * STAGE_BYTES;

        #pragma unroll
        for (int ks = 0; ks < 4; ks++) {
            const int ca = 2 * ks + aCSel;
            const int cb = 2 * ks + bCSel;
            uint32_t a[2][4], b[8][2];
            #pragma unroll
            for (int mt = 0; mt < 2; mt++)
                ldsm_x4(a[mt], stg + aBase[mt] + (uint32_t)((ca ^ aPar[mt]) << 4));
            #pragma unroll
            for (int nt = 0; nt < 8; nt++)
                ldsm_x2(b[nt], stg + bBase[nt] + (uint32_t)((cb ^ bPar[nt]) << 4));
            #pragma unroll
            for (int mt = 0; mt < 2; mt++)
                #pragma unroll
                for (int nt = 0; nt < 8; nt++)
                    mma_tf32(acc[mt][nt], a[mt], b[nt]);
        }
        __syncthreads();
    }

    #pragma unroll
    for (int mt = 0; mt < 2; mt++) {
        const int rm = blockIdx.y * 128 + m0w + mt * 16 + g;
        const float bv0 = (MBIAS == 1) ? __ldg(bias + rm)     : 0.0f;
        const float bv1 = (MBIAS == 1) ? __ldg(bias + rm + 8) : 0.0f;
        #pragma unroll
        for (int nt = 0; nt < 8; nt++) {
            const int cn = n0w + nt * 8 + t * 2;
            float cb0 = 0.0f, cb1 = 0.0f;
            if (MBIAS == 2) {
                cb0 = __ldg(bias + blockIdx.x * 128 + cn);
                cb1 = __ldg(bias + blockIdx.x * 128 + cn + 1);
            }
            float2 v0, v1;
            v0.x = alpha * acc[mt][nt][0] + bv0 + cb0;
            v0.y = alpha * acc[mt][nt][1] + bv0 + cb1;
            v1.x = alpha * acc[mt][nt][2] + bv1 + cb0;
            v1.y = alpha * acc[mt][nt][3] + bv1 + cb1;
            if (RND) {
                v0.x = rtf(v0.x); v0.y = rtf(v0.y);
                v1.x = rtf(v1.x); v1.y = rtf(v1.y);
            }
            const int r = m0w + mt * 16 + g;
            *reinterpret_cast<float2*>(&Cb[(size_t)r * ldc + cn]) = v0;
            *reinterpret_cast<float2*>(&Cb[(size_t)(r + 8) * ldc + cn]) = v1;
        }
    }
}

// ---------------------------------------------------------------------------
__global__ __launch_bounds__(256) void round_tf32(
    const float* __restrict__ in, float* __restrict__ out)
{
    const size_t i = (size_t)blockIdx.x * 256 + threadIdx.x;
    float4 v = reinterpret_cast<const float4*>(in)[i];
    v.x = rtf(v.x); v.y = rtf(v.y); v.z = rtf(v.z); v.w = rtf(v.w);
    reinterpret_cast<float4*>(out)[i] = v;
}

// ---------------------------------------------------------------------------
// Generic transpose with tf32 rounding: in (R x C) -> out (C x R)
// ---------------------------------------------------------------------------
__global__ void transpose_rnd(const float* __restrict__ in, float* __restrict__ out,
                              int R, int C)
{
    __shared__ float tb[32][33];
    const int c0 = blockIdx.x * 32, r0 = blockIdx.y * 32;
    const int tx = threadIdx.x, ty = threadIdx.y;
    #pragma unroll
    for (int j = 0; j < 32; j += 8)
        tb[ty + j][tx] = in[(size_t)(r0 + ty + j) * C + c0 + tx];
    __syncthreads();
    #pragma unroll
    for (int j = 0; j < 32; j += 8)
        out[(size_t)(c0 + ty + j) * R + r0 + tx] = rtf(tb[tx][ty + j]);
}

// ---------------------------------------------------------------------------
// Batched transpose of x: [b][512][1024] -> xT [b][1024][512], rounded
// ---------------------------------------------------------------------------
__global__ void transpose_x(const float* __restrict__ in, float* __restrict__ out)
{
    __shared__ float tb[32][33];
    const int n0 = blockIdx.x * 32, c0 = blockIdx.y * 32;
    const float* ib = in  + (size_t)blockIdx.z * CIND * NTOK;
    float*       ob = out + (size_t)blockIdx.z * NTOK * CIND;
    const int tx = threadIdx.x, ty = threadIdx.y;
    #pragma unroll
    for (int j = 0; j < 32; j += 8)
        tb[ty + j][tx] = ib[(size_t)(c0 + ty + j) * NTOK + n0 + tx];
    __syncthreads();
    #pragma unroll
    for (int j = 0; j < 32; j += 8)
        ob[(size_t)(n0 + ty + j) * CIND + c0 + tx] = rtf(tb[tx][ty + j]);
}

// ---------------------------------------------------------------------------
// bq[r] = sum_e W[r][e] * b[e]   (fp32 GEMV, W is EMBD x EMBD)
// ---------------------------------------------------------------------------
__global__ __launch_bounds__(256) void gemv_bias(
    const float* __restrict__ W, const float* __restrict__ b, float* __restrict__ out)
{
    __shared__ float red[256];
    const int r = blockIdx.x;
    float s = 0.0f;
    for (int e = threadIdx.x; e < EMBD; e += 256)
        s += W[(size_t)r * EMBD + e] * b[e];
    red[threadIdx.x] = s;
    __syncthreads();
    for (int o = 128; o; o >>= 1) {
        if (threadIdx.x < o) red[threadIdx.x] += red[threadIdx.x + o];
        __syncthreads();
    }
    if (threadIdx.x == 0) out[r] = red[0];
}

// ---------------------------------------------------------------------------
__global__ __launch_bounds__(256) void softmax_rows(
    float* __restrict__ S, float* __restrict__ SR,
    const unsigned char* __restrict__ mask)
{
    const size_t row = blockIdx.x;
    float4* p  = reinterpret_cast<float4*>(S  + row * SEQL);
    float4* pr = reinterpret_cast<float4*>(SR + row * SEQL);
    const uchar4* mp = reinterpret_cast<const uchar4*>(mask + row * SEQL);
    const int t = threadIdx.x;

    float4 v = p[t];
    uchar4 m = mp[t];
    if (m.x) v.x = -1e9f;
    if (m.y) v.y = -1e9f;
    if (m.z) v.z = -1e9f;
    if (m.w) v.w = -1e9f;

    float mx = fmaxf(fmaxf(v.x, v.y), fmaxf(v.z, v.w));
    #pragma unroll
    for (int o = 16; o; o >>= 1) mx = fmaxf(mx, __shfl_xor_sync(0xffffffffu, mx, o));
    __shared__ float sm[8];
    const int w = t >> 5;
    if ((t & 31) == 0) sm[w] = mx;
    __syncthreads();
    float rmax = sm[0];
    #pragma unroll
    for (int i = 1; i < 8; i++) rmax = fmaxf(rmax, sm[i]);

    v.x = __expf(v.x - rmax); v.y = __expf(v.y - rmax);
    v.z = __expf(v.z - rmax); v.w = __expf(v.w - rmax);

    float s = v.x + v.y + v.z + v.w;
    #pragma unroll
    for (int o = 16; o; o >>= 1) s += __shfl_xor_sync(0xffffffffu, s, o);
    __shared__ float ss[8];
    if ((t & 31) == 0) ss[w] = s;
    __syncthreads();
    float tot = 0.0f;
    #pragma unroll
    for (int i = 0; i < 8; i++) tot += ss[i];

    float inv = 1.0f / tot;
    v.x *= inv; v.y *= inv; v.z *= inv; v.w *= inv;
    p[t] = v;
    float4 r;
    r.x = rtf(v.x); r.y = rtf(v.y); r.z = rtf(v.z); r.w = rtf(v.w);
    pr[t] = r;
}

// ---------------------------------------------------------------------------
extern "C" void kernel_launch(void* const* d_in, const int* in_sizes, int n_in,
                              void* d_out, int out_size)
{
    const float* x       = (const float*)d_in[0];
    const float* content = (const float*)d_in[1];
    const unsigned char* pmask = (const unsigned char*)d_in[2];
    const float* W_in    = (const float*)d_in[3];
    const float* b_in    = (const float*)d_in[4];
    const float* Wq      = (const float*)d_in[5];
    const float* Wk      = (const float*)d_in[6];
    const float* Wv      = (const float*)d_in[7];
    const float* W_out   = (const float*)d_in[8];
    const float* b_out   = (const float*)d_in[9];

    float* out = (float*)d_out;                       // (8,512,32,32)
    float* att = out + (size_t)BATCH * CIND * NTOK;   // (8,1024,1024)

    float *xT, *Q, *Kp, *Ct, *aR, *Ut, *Wq2, *Wk2, *Wit, *Wqi, *bq, *Wo2, *Wvt, *Wvo;
    cudaGetSymbolAddress((void**)&xT,  g_xT);
    cudaGetSymbolAddress((void**)&Q,   g_Q);
    cudaGetSymbolAddress((void**)&Kp,  g_K);
    cudaGetSymbolAddress((void**)&Ct,  g_Ct);
    cudaGetSymbolAddress((void**)&aR,  g_aR);
    cudaGetSymbolAddress((void**)&Ut,  g_Ut);
    cudaGetSymbolAddress((void**)&Wq2, g_Wq2);
    cudaGetSymbolAddress((void**)&Wk2, g_Wk2);
    cudaGetSymbolAddress((void**)&Wit, g_Wit);
    cudaGetSymbolAddress((void**)&Wqi, g_Wqi);
    cudaGetSymbolAddress((void**)&bq,  g_bq);
    cudaGetSymbolAddress((void**)&Wo2, g_Wo2);
    cudaGetSymbolAddress((void**)&Wvt, g_Wvt);
    cudaGetSymbolAddress((void**)&Wvo, g_Wvo);

    cudaFuncSetAttribute(tc_gemm<0,0>, cudaFuncAttributeMaxDynamicSharedMemorySize, SMEM_BYTES);
    cudaFuncSetAttribute(tc_gemm<0,1>, cudaFuncAttributeMaxDynamicSharedMemorySize, SMEM_BYTES);
    cudaFuncSetAttribute(tc_gemm<1,0>, cudaFuncAttributeMaxDynamicSharedMemorySize, SMEM_BYTES);
    cudaFuncSetAttribute(tc_gemm<2,1>, cudaFuncAttributeMaxDynamicSharedMemorySize, SMEM_BYTES);

    static cudaStream_t s1 = nullptr;
    static cudaEvent_t eF = nullptr, eK = nullptr, eU = nullptr;
    if (s1 == nullptr) {
        cudaStreamCreateWithFlags(&s1, cudaStreamNonBlocking);
        cudaEventCreateWithFlags(&eF, cudaEventDisableTiming);
        cudaEventCreateWithFlags(&eK, cudaEventDisableTiming);
        cudaEventCreateWithFlags(&eU, cudaEventDisableTiming);
    }

    const size_t EN = (size_t)NTOK * EMBD;
    const size_t SE = (size_t)SEQL * EMBD;
    const size_t NS = (size_t)NTOK * SEQL;
    const size_t XC = (size_t)NTOK * CIND;
    const size_t CS = (size_t)CIND * SEQL;
    const size_t CN = (size_t)CIND * NTOK;
    const float scale = 1.0f / 32.0f;

    // ---- fork side stream ----
    cudaEventRecord(eF, 0);
    cudaStreamWaitEvent(s1, eF, 0);

    // ======== s1: content / K / Ut chain ========
    round_tf32<<<(EMBD * EMBD) / 1024, 256, 0, s1>>>(Wk, Wk2);
    round_tf32<<<(BATCH * SE) / 1024, 256, 0, s1>>>(content, Ct);
    // K[s][e'] = Ct[s][e]·Wk2[e'][e]
    tc_gemm<0,1><<<dim3(8, 8, BATCH), 256, SMEM_BYTES, s1>>>(
        Ct, Wk2, Kp, nullptr, EMBD, EMBD, SE, 0, SE, 1.0f);
    cudaEventRecord(eK, s1);
    round_tf32<<<(CIND * EMBD) / 1024, 256, 0, s1>>>(W_out, Wo2);
    transpose_rnd<<<dim3(EMBD / 32, EMBD / 32), dim3(32, 8), 0, s1>>>(Wv, Wvt, EMBD, EMBD);
    // Wvo[c][d] = Wo2[c][e]·Wvt[d][e]
    tc_gemm<0,1><<<dim3(8, 4, 1), 256, SMEM_BYTES, s1>>>(
        Wo2, Wvt, Wvo, nullptr, EMBD, EMBD, 0, 0, 0, 1.0f);
    // Ut[c][s] = Wvo[c][d]·Ct[s][d]
    tc_gemm<0,1><<<dim3(8, 4, BATCH), 256, SMEM_BYTES, s1>>>(
        Wvo, Ct, Ut, nullptr, EMBD, SEQL, 0, SE, CS, 1.0f);
    cudaEventRecord(eU, s1);

    // ======== s0: x / Q chain ========
    transpose_rnd<<<dim3(CIND / 32, EMBD / 32), dim3(32, 8)>>>(W_in, Wit, EMBD, CIND);
    round_tf32<<<(EMBD * EMBD) / 1024, 256>>>(Wq, Wq2);
    // Wqi[e'][c] = Wq2[e'][e]·Wit[c][e]
    tc_gemm<0,1><<<dim3(4, 8, 1), 256, SMEM_BYTES>>>(
        Wq2, Wit, Wqi, nullptr, EMBD, CIND, 0, 0, 0, 1.0f);
    gemv_bias<<<EMBD, 256>>>(Wq, b_in, bq);
    transpose_x<<<dim3(NTOK / 32, CIND / 32, BATCH), dim3(32, 8)>>>(x, xT);
    // Q[n][e'] = xT[n][c]·Wqi[e'][c] + bq[e']  (col bias)
    tc_gemm<2,1><<<dim3(8, 8, BATCH), 256, SMEM_BYTES>>>(
        xT, Wqi, Q, bq, CIND, EMBD, XC, 0, EN, 1.0f);

    // ---- join for scores (needs K) ----
    cudaStreamWaitEvent(0, eK, 0);
    // att = scale * Q·K^T  (exact -> d_out att region)
    tc_gemm<0,0><<<dim3(8, 8, BATCH), 256, SMEM_BYTES>>>(
        Q, Kp, att, nullptr, EMBD, SEQL, EN, SE, NS, scale);

    softmax_rows<<<BATCH * NTOK, 256>>>(att, aR, pmask);

    // ---- join for output (needs Ut) ----
    cudaStreamWaitEvent(0, eU, 0);
    // out[c][n] = Ut[c][j]·aR[n][j] + b_out[c]  (row bias)
    tc_gemm<1,0><<<dim3(8, 4, BATCH), 256, SMEM_BYTES>>>(
        Ut, aR, out, b_out, SEQL, NTOK, CS, NS, CN, 1.0f);
}

// round 9
// speedup vs baseline: 7.3248x; 1.0543x over previous
#include <cuda_runtime.h>
#include <cstdint>

#define BATCH 8
#define EMBD  1024
#define CIND  512
#define NTOK  1024
#define SEQL  1024

// ---------------- scratch (device globals; allocation-free) ----------------
__device__ float g_xT [(size_t)BATCH * NTOK * CIND];  // x^T, tf32-rounded
__device__ float g_K  [(size_t)BATCH * SEQL * EMBD];  // K (rounded)
__device__ float g_Ct [(size_t)BATCH * SEQL * EMBD];  // rounded content
__device__ float g_Zt [(size_t)BATCH * SEQL * CIND];  // Zt[s][c] = K·Wqi (rounded)
__device__ float g_beta[(size_t)BATCH * SEQL];        // scale * K·bq  (fp32)
__device__ float g_aR [(size_t)BATCH * NTOK * SEQL];  // rounded copy of att
__device__ float g_Ut [(size_t)BATCH * CIND * SEQL];  // Ut[c][s]
__device__ float g_Wq2[EMBD * EMBD];                  // rounded Wq
__device__ float g_Wk2[EMBD * EMBD];                  // rounded Wk
__device__ float g_Wit[CIND * EMBD];                  // W_in^T rounded
__device__ float g_WqiT[CIND * EMBD];                 // (Wq·W_in)^T : [c][e']
__device__ float g_bq [EMBD];                         // Wq·b_in (fp32)
__device__ float g_Wo2[CIND * EMBD];                  // rounded W_out
__device__ float g_Wvt[EMBD * EMBD];                  // Wv^T rounded
__device__ float g_Wvo[CIND * EMBD];                  // folded W_out·Wv

// ---------------- helpers ----------------
__device__ __forceinline__ uint32_t smem_u32(const void* p) {
    uint32_t a;
    asm("{ .reg .u64 t; cvta.to.shared.u64 t, %1; cvt.u32.u64 %0, t; }" : "=r"(a) : "l"(p));
    return a;
}
__device__ __forceinline__ uint32_t f2tf(float x) {
    uint32_t r; asm("cvt.rna.tf32.f32 %0, %1;" : "=r"(r) : "f"(x)); return r;
}
__device__ __forceinline__ float rtf(float x) { return __uint_as_float(f2tf(x)); }

#define CP_ASYNC16(dst, src) \
    asm volatile("cp.async.cg.shared.global.L2::128B [%0], [%1], 16;" \
                 :: "r"(dst), "l"(src) : "memory")
#define CP_COMMIT() asm volatile("cp.async.commit_group;" ::: "memory")
#define CP_WAIT1()  asm volatile("cp.async.wait_group 1;" ::: "memory")

__device__ __forceinline__ void ldsm_x4(uint32_t* r, uint32_t a) {
    asm volatile("ldmatrix.sync.aligned.m8n8.x4.shared.b16 {%0,%1,%2,%3}, [%4];"
                 : "=r"(r[0]), "=r"(r[1]), "=r"(r[2]), "=r"(r[3]) : "r"(a));
}
__device__ __forceinline__ void ldsm_x2(uint32_t* r, uint32_t a) {
    asm volatile("ldmatrix.sync.aligned.m8n8.x2.shared.b16 {%0,%1}, [%2];"
                 : "=r"(r[0]), "=r"(r[1]) : "r"(a));
}
__device__ __forceinline__ void mma_tf32(float* d, const uint32_t* a, const uint32_t* b) {
    asm volatile(
        "mma.sync.aligned.m16n8k8.row.col.f32.tf32.tf32.f32 "
        "{%0,%1,%2,%3}, {%4,%5,%6,%7}, {%8,%9}, {%0,%1,%2,%3};"
        : "+f"(d[0]), "+f"(d[1]), "+f"(d[2]), "+f"(d[3])
        : "r"(a[0]), "r"(a[1]), "r"(a[2]), "r"(a[3]), "r"(b[0]), "r"(b[1]));
}

// ---------------------------------------------------------------------------
// TF32 tensor-core GEMM:  C[m][n] = alpha * sum_k A[m][k] * B[n][k] (+bias)
// A, B K-major, row stride == K, PRE-ROUNDED to tf32 in memory.
// Block tile 128x128, BK=32, 3-stage cp.async pipeline.
// 128 threads = 4 warps in 2x2, warp tile 64x64 (halves smem re-reads vs 8x).
// MBIAS: 0 none, 1 row bias (per m), 2 batched col bias (bias + bz*sBias + n).
// RND: round C to tf32 at store.
// ---------------------------------------------------------------------------
#define STAGE_BYTES 32768
#define SMEM_BYTES  (3 * STAGE_BYTES)

template<int MBIAS, int RND>
__global__ __launch_bounds__(128, 2) void tc_gemm(
    const float* __restrict__ A, const float* __restrict__ B,
    float* __restrict__ C, const float* __restrict__ bias,
    int K, int ldc, size_t sA, size_t sB, size_t sC, size_t sBias, float alpha)
{
    extern __shared__ char smem[];
    const uint32_t sbase = smem_u32(smem);
    const int tid  = threadIdx.x;
    const int wid  = tid >> 5, lane = tid & 31;
    const int g = lane >> 2, t = lane & 3;
    const int m0w = (wid & 1) * 64;
    const int n0w = (wid >> 1) * 64;

    const float* Ab = A + blockIdx.z * sA + (size_t)(blockIdx.y * 128) * K;
    const float* Bb = B + blockIdx.z * sB + (size_t)(blockIdx.x * 128) * K;
    float*       Cb = C + blockIdx.z * sC + (size_t)(blockIdx.y * 128) * ldc
                        + blockIdx.x * 128;

    // cp.async fill: 128 threads, 8 A-chunks + 8 B-chunks each
    const int fr = tid >> 3;          // 0..15
    const int fq = tid & 7;

    auto issue = [&](int stage) {
        const uint32_t sa = sbase + (stage % 3) * STAGE_BYTES;
        const int k0 = stage * 32;
        #pragma unroll
        for (int i = 0; i < 8; i++) {
            const int r = fr + i * 16;
            const uint32_t dst = sa + r * 128 + ((fq ^ (r & 7)) << 4);
            CP_ASYNC16(dst, Ab + (size_t)r * K + k0 + fq * 4);
        }
        #pragma unroll
        for (int i = 0; i < 8; i++) {
            const int r = fr + i * 16;
            const uint32_t dst = sa + 16384 + r * 128 + ((fq ^ (r & 7)) << 4);
            CP_ASYNC16(dst, Bb + (size_t)r * K + k0 + fq * 4);
        }
    };

    // ldmatrix per-lane bases
    const int aRow8 = (lane & 7) + ((lane >> 3) & 1) * 8;
    const int aCSel = (lane >> 4) & 1;
    uint32_t aBase[4]; int aPar[4];
    #pragma unroll
    for (int mt = 0; mt < 4; mt++) {
        const int r = m0w + mt * 16 + aRow8;
        aBase[mt] = (uint32_t)r * 128;
        aPar[mt]  = r & 7;
    }
    const int bCSel = (lane >> 3) & 1;
    uint32_t bBase[8]; int bPar[8];
    #pragma unroll
    for (int nt = 0; nt < 8; nt++) {
        const int r = n0w + nt * 8 + (lane & 7);
        bBase[nt] = 16384u + (uint32_t)r * 128;
        bPar[nt]  = r & 7;
    }

    float acc[4][8][4];
    #pragma unroll
    for (int mt = 0; mt < 4; mt++)
        #pragma unroll
        for (int nt = 0; nt < 8; nt++)
            #pragma unroll
            for (int i = 0; i < 4; i++) acc[mt][nt][i] = 0.0f;

    const int NC = K >> 5;
    issue(0); CP_COMMIT();
    issue(1); CP_COMMIT();

    for (int c = 0; c < NC; c++) {
        CP_WAIT1();
        __syncthreads();
        if (c + 2 < NC) issue(c + 2);
        CP_COMMIT();

        const uint32_t stg = sbase + (c % 3) * STAGE_BYTES;

        #pragma unroll
        for (int ks = 0; ks < 4; ks++) {
            const int ca = 2 * ks + aCSel;
            const int cb = 2 * ks + bCSel;
            uint32_t a[4][4], b[8][2];
            #pragma unroll
            for (int mt = 0; mt < 4; mt++)
                ldsm_x4(a[mt], stg + aBase[mt] + (uint32_t)((ca ^ aPar[mt]) << 4));
            #pragma unroll
            for (int nt = 0; nt < 8; nt++)
                ldsm_x2(b[nt], stg + bBase[nt] + (uint32_t)((cb ^ bPar[nt]) << 4));
            #pragma unroll
            for (int mt = 0; mt < 4; mt++)
                #pragma unroll
                for (int nt = 0; nt < 8; nt++)
                    mma_tf32(acc[mt][nt], a[mt], b[nt]);
        }
        __syncthreads();
    }

    #pragma unroll
    for (int mt = 0; mt < 4; mt++) {
        const int rm = blockIdx.y * 128 + m0w + mt * 16 + g;
        const float bv0 = (MBIAS == 1) ? __ldg(bias + rm)     : 0.0f;
        const float bv1 = (MBIAS == 1) ? __ldg(bias + rm + 8) : 0.0f;
        #pragma unroll
        for (int nt = 0; nt < 8; nt++) {
            const int cn = n0w + nt * 8 + t * 2;
            float cb0 = 0.0f, cb1 = 0.0f;
            if (MBIAS == 2) {
                const float* bb = bias + blockIdx.z * sBias + blockIdx.x * 128 + cn;
                cb0 = __ldg(bb);
                cb1 = __ldg(bb + 1);
            }
            float2 v0, v1;
            v0.x = alpha * acc[mt][nt][0] + bv0 + cb0;
            v0.y = alpha * acc[mt][nt][1] + bv0 + cb1;
            v1.x = alpha * acc[mt][nt][2] + bv1 + cb0;
            v1.y = alpha * acc[mt][nt][3] + bv1 + cb1;
            if (RND) {
                v0.x = rtf(v0.x); v0.y = rtf(v0.y);
                v1.x = rtf(v1.x); v1.y = rtf(v1.y);
            }
            const int r = m0w + mt * 16 + g;
            *reinterpret_cast<float2*>(&Cb[(size_t)r * ldc + cn]) = v0;
            *reinterpret_cast<float2*>(&Cb[(size_t)(r + 8) * ldc + cn]) = v1;
        }
    }
}

// ---------------------------------------------------------------------------
__global__ __launch_bounds__(256) void round_tf32(
    const float* __restrict__ in, float* __restrict__ out)
{
    const size_t i = (size_t)blockIdx.x * 256 + threadIdx.x;
    float4 v = reinterpret_cast<const float4*>(in)[i];
    v.x = rtf(v.x); v.y = rtf(v.y); v.z = rtf(v.z); v.w = rtf(v.w);
    reinterpret_cast<float4*>(out)[i] = v;
}

// ---------------------------------------------------------------------------
__global__ void transpose_rnd(const float* __restrict__ in, float* __restrict__ out,
                              int R, int C)
{
    __shared__ float tb[32][33];
    const int c0 = blockIdx.x * 32, r0 = blockIdx.y * 32;
    const int tx = threadIdx.x, ty = threadIdx.y;
    #pragma unroll
    for (int j = 0; j < 32; j += 8)
        tb[ty + j][tx] = in[(size_t)(r0 + ty + j) * C + c0 + tx];
    __syncthreads();
    #pragma unroll
    for (int j = 0; j < 32; j += 8)
        out[(size_t)(c0 + ty + j) * R + r0 + tx] = rtf(tb[tx][ty + j]);
}

// ---------------------------------------------------------------------------
__global__ void transpose_x(const float* __restrict__ in, float* __restrict__ out)
{
    __shared__ float tb[32][33];
    const int n0 = blockIdx.x * 32, c0 = blockIdx.y * 32;
    const float* ib = in  + (size_t)blockIdx.z * CIND * NTOK;
    float*       ob = out + (size_t)blockIdx.z * NTOK * CIND;
    const int tx = threadIdx.x, ty = threadIdx.y;
    #pragma unroll
    for (int j = 0; j < 32; j += 8)
        tb[ty + j][tx] = ib[(size_t)(c0 + ty + j) * NTOK + n0 + tx];
    __syncthreads();
    #pragma unroll
    for (int j = 0; j < 32; j += 8)
        ob[(size_t)(n0 + ty + j) * CIND + c0 + tx] = rtf(tb[tx][ty + j]);
}

// ---------------------------------------------------------------------------
// bq[r] = sum_e Wq[r][e] * b_in[e]   (fp32 GEMV)
// ---------------------------------------------------------------------------
__global__ __launch_bounds__(256) void gemv_bias(
    const float* __restrict__ W, const float* __restrict__ b, float* __restrict__ out)
{
    __shared__ float red[256];
    const int r = blockIdx.x;
    float s = 0.0f;
    for (int e = threadIdx.x; e < EMBD; e += 256)
        s += W[(size_t)r * EMBD + e] * b[e];
    red[threadIdx.x] = s;
    __syncthreads();
    for (int o = 128; o; o >>= 1) {
        if (threadIdx.x < o) red[threadIdx.x] += red[threadIdx.x + o];
        __syncthreads();
    }
    if (threadIdx.x == 0) out[r] = red[0];
}

// ---------------------------------------------------------------------------
// beta[row] = scale * sum_e K[row][e] * bq[e]   (one warp per row, fp32)
// ---------------------------------------------------------------------------
__global__ __launch_bounds__(256) void beta_rows(
    const float* __restrict__ Km, const float* __restrict__ bq,
    float* __restrict__ beta, float scale)
{
    const int row = blockIdx.x * 8 + (threadIdx.x >> 5);
    const int lane = threadIdx.x & 31;
    const float* kr = Km + (size_t)row * EMBD;
    float s = 0.0f;
    #pragma unroll 4
    for (int e = lane; e < EMBD; e += 32) s += kr[e] * bq[e];
    #pragma unroll
    for (int o = 16; o; o >>= 1) s += __shfl_xor_sync(0xffffffffu, s, o);
    if (lane == 0) beta[row] = scale * s;
}

// ---------------------------------------------------------------------------
__global__ __launch_bounds__(256) void softmax_rows(
    float* __restrict__ S, float* __restrict__ SR,
    const unsigned char* __restrict__ mask)
{
    const size_t row = blockIdx.x;
    float4* p  = reinterpret_cast<float4*>(S  + row * SEQL);
    float4* pr = reinterpret_cast<float4*>(SR + row * SEQL);
    const uchar4* mp = reinterpret_cast<const uchar4*>(mask + row * SEQL);
    const int t = threadIdx.x;

    float4 v = p[t];
    uchar4 m = mp[t];
    if (m.x) v.x = -1e9f;
    if (m.y) v.y = -1e9f;
    if (m.z) v.z = -1e9f;
    if (m.w) v.w = -1e9f;

    float mx = fmaxf(fmaxf(v.x, v.y), fmaxf(v.z, v.w));
    #pragma unroll
    for (int o = 16; o; o >>= 1) mx = fmaxf(mx, __shfl_xor_sync(0xffffffffu, mx, o));
    __shared__ float sm[8];
    const int w = t >> 5;
    if ((t & 31) == 0) sm[w] = mx;
    __syncthreads();
    float rmax = sm[0];
    #pragma unroll
    for (int i = 1; i < 8; i++) rmax = fmaxf(rmax, sm[i]);

    v.x = __expf(v.x - rmax); v.y = __expf(v.y - rmax);
    v.z = __expf(v.z - rmax); v.w = __expf(v.w - rmax);

    float s = v.x + v.y + v.z + v.w;
    #pragma unroll
    for (int o = 16; o; o >>= 1) s += __shfl_xor_sync(0xffffffffu, s, o);
    __shared__ float ss[8];
    if ((t & 31) == 0) ss[w] = s;
    __syncthreads();
    float tot = 0.0f;
    #pragma unroll
    for (int i = 0; i < 8; i++) tot += ss[i];

    float inv = 1.0f / tot;
    v.x *= inv; v.y *= inv; v.z *= inv; v.w *= inv;
    p[t] = v;
    float4 r;
    r.x = rtf(v.x); r.y = rtf(v.y); r.z = rtf(v.z); r.w = rtf(v.w);
    pr[t] = r;
}

// ---------------------------------------------------------------------------
extern "C" void kernel_launch(void* const* d_in, const int* in_sizes, int n_in,
                              void* d_out, int out_size)
{
    const float* x       = (const float*)d_in[0];
    const float* content = (const float*)d_in[1];
    const unsigned char* pmask = (const unsigned char*)d_in[2];
    const float* W_in    = (const float*)d_in[3];
    const float* b_in    = (const float*)d_in[4];
    const float* Wq      = (const float*)d_in[5];
    const float* Wk      = (const float*)d_in[6];
    const float* Wv      = (const float*)d_in[7];
    const float* W_out   = (const float*)d_in[8];
    const float* b_out   = (const float*)d_in[9];

    float* out = (float*)d_out;                       // (8,512,32,32)
    float* att = out + (size_t)BATCH * CIND * NTOK;   // (8,1024,1024)

    float *xT, *Kp, *Ct, *Zt, *beta, *aR, *Ut, *Wq2, *Wk2, *Wit, *WqiT, *bq, *Wo2, *Wvt, *Wvo;
    cudaGetSymbolAddress((void**)&xT,   g_xT);
    cudaGetSymbolAddress((void**)&Kp,   g_K);
    cudaGetSymbolAddress((void**)&Ct,   g_Ct);
    cudaGetSymbolAddress((void**)&Zt,   g_Zt);
    cudaGetSymbolAddress((void**)&beta, g_beta);
    cudaGetSymbolAddress((void**)&aR,   g_aR);
    cudaGetSymbolAddress((void**)&Ut,   g_Ut);
    cudaGetSymbolAddress((void**)&Wq2,  g_Wq2);
    cudaGetSymbolAddress((void**)&Wk2,  g_Wk2);
    cudaGetSymbolAddress((void**)&Wit,  g_Wit);
    cudaGetSymbolAddress((void**)&WqiT, g_WqiT);
    cudaGetSymbolAddress((void**)&bq,   g_bq);
    cudaGetSymbolAddress((void**)&Wo2,  g_Wo2);
    cudaGetSymbolAddress((void**)&Wvt,  g_Wvt);
    cudaGetSymbolAddress((void**)&Wvo,  g_Wvo);

    cudaFuncSetAttribute(tc_gemm<0,1>, cudaFuncAttributeMaxDynamicSharedMemorySize, SMEM_BYTES);
    cudaFuncSetAttribute(tc_gemm<1,0>, cudaFuncAttributeMaxDynamicSharedMemorySize, SMEM_BYTES);
    cudaFuncSetAttribute(tc_gemm<2,0>, cudaFuncAttributeMaxDynamicSharedMemorySize, SMEM_BYTES);

    static cudaStream_t s1 = nullptr;
    static cudaEvent_t eF = nullptr, eCt = nullptr, eZ = nullptr;
    if (s1 == nullptr) {
        cudaStreamCreateWithFlags(&s1, cudaStreamNonBlocking);
        cudaEventCreateWithFlags(&eF,  cudaEventDisableTiming);
        cudaEventCreateWithFlags(&eCt, cudaEventDisableTiming);
        cudaEventCreateWithFlags(&eZ,  cudaEventDisableTiming);
    }

    const size_t SE  = (size_t)SEQL * EMBD;
    const size_t NS  = (size_t)NTOK * SEQL;
    const size_t NSc = (size_t)SEQL * CIND;
    const size_t XC  = (size_t)NTOK * CIND;
    const size_t CS  = (size_t)CIND * SEQL;
    const size_t CN  = (size_t)CIND * NTOK;
    const float scale = 1.0f / 32.0f;

    // ---- fork side stream ----
    cudaEventRecord(eF, 0);
    cudaStreamWaitEvent(s1, eF, 0);

    // ======== s1: scores chain (K -> Zt) ========
    round_tf32<<<(EMBD * EMBD) / 1024, 256, 0, s1>>>(Wq, Wq2);
    transpose_rnd<<<dim3(CIND / 32, EMBD / 32), dim3(32, 8), 0, s1>>>(W_in, Wit, EMBD, CIND);
    // WqiT[c][e'] = Wit[c][e]·Wq2[e'][e]
    tc_gemm<0,1><<<dim3(8, 4, 1), 128, SMEM_BYTES, s1>>>(
        Wit, Wq2, WqiT, nullptr, EMBD, EMBD, 0, 0, 0, 0, 1.0f);
    round_tf32<<<(BATCH * SE) / 1024, 256, 0, s1>>>(content, Ct);
    cudaEventRecord(eCt, s1);
    round_tf32<<<(EMBD * EMBD) / 1024, 256, 0, s1>>>(Wk, Wk2);
    // K[s][e'] = Ct[s][e]·Wk2[e'][e]
    tc_gemm<0,1><<<dim3(8, 8, BATCH), 128, SMEM_BYTES, s1>>>(
        Ct, Wk2, Kp, nullptr, EMBD, EMBD, SE, 0, SE, 0, 1.0f);
    gemv_bias<<<EMBD, 256, 0, s1>>>(Wq, b_in, bq);
    beta_rows<<<(BATCH * SEQL) / 8, 256, 0, s1>>>(Kp, bq, beta, scale);
    // Zt[s][c] = Kp[s][e']·WqiT[c][e']
    tc_gemm<0,1><<<dim3(4, 8, BATCH), 128, SMEM_BYTES, s1>>>(
        Kp, WqiT, Zt, nullptr, EMBD, CIND, SE, 0, NSc, 0, 1.0f);
    cudaEventRecord(eZ, s1);

    // ======== s0: x / out-side prep ========
    transpose_x<<<dim3(NTOK / 32, CIND / 32, BATCH), dim3(32, 8)>>>(x, xT);
    round_tf32<<<(CIND * EMBD) / 1024, 256>>>(W_out, Wo2);
    transpose_rnd<<<dim3(EMBD / 32, EMBD / 32), dim3(32, 8)>>>(Wv, Wvt, EMBD, EMBD);
    // Wvo[c][d] = Wo2[c][e]·Wvt[d][e]
    tc_gemm<0,1><<<dim3(8, 4, 1), 128, SMEM_BYTES>>>(
        Wo2, Wvt, Wvo, nullptr, EMBD, EMBD, 0, 0, 0, 0, 1.0f);
    // Ut[c][s] = Wvo[c][d]·Ct[s][d]   (needs Ct)
    cudaStreamWaitEvent(0, eCt, 0);
    tc_gemm<0,1><<<dim3(8, 4, BATCH), 128, SMEM_BYTES>>>(
        Wvo, Ct, Ut, nullptr, EMBD, SEQL, 0, SE, CS, 0, 1.0f);

    // ---- scores: att[n][s] = scale·xT[n][c]·Zt[s][c] + beta[b][s] ----
    cudaStreamWaitEvent(0, eZ, 0);
    tc_gemm<2,0><<<dim3(8, 8, BATCH), 128, SMEM_BYTES>>>(
        xT, Zt, att, beta, CIND, SEQL, XC, NSc, NS, SEQL, scale);

    softmax_rows<<<BATCH * NTOK, 256>>>(att, aR, pmask);

    // out[c][n] = Ut[c][j]·aR[n][j] + b_out[c]
    tc_gemm<1,0><<<dim3(8, 4, BATCH), 128, SMEM_BYTES>>>(
        Ut, aR, out, b_out, SEQL, NTOK, CS, NS, CN, 0, 1.0f);
}

// round 11
// speedup vs baseline: 8.8661x; 1.2104x over previous
#include <cuda_runtime.h>
#include <cstdint>

#define BATCH 8
#define HALFB 4
#define EMBD  1024
#define CIND  512
#define NTOK  1024
#define SEQL  1024

// ---------------- scratch (device globals; allocation-free) ----------------
__device__ float g_xT [(size_t)BATCH * NTOK * CIND];  // x^T, tf32-rounded
__device__ float g_K  [(size_t)BATCH * SEQL * EMBD];  // K (rounded)
__device__ float g_Ct [(size_t)BATCH * SEQL * EMBD];  // rounded content
__device__ float g_Zt [(size_t)BATCH * SEQL * CIND];  // Zt[s][c] = K·Wqi (rounded)
__device__ float g_beta[(size_t)BATCH * SEQL];        // scale * K·bq  (fp32)
__device__ float g_aR [(size_t)BATCH * NTOK * SEQL];  // rounded copy of att
__device__ float g_Ut [(size_t)BATCH * CIND * SEQL];  // Ut[c][s]
__device__ float g_Wq2[EMBD * EMBD];                  // rounded Wq
__device__ float g_Wk2[EMBD * EMBD];                  // rounded Wk
__device__ float g_Wit[CIND * EMBD];                  // W_in^T rounded
__device__ float g_WqiT[CIND * EMBD];                 // (Wq·W_in)^T : [c][e']
__device__ float g_bq [EMBD];                         // Wq·b_in (fp32)
__device__ float g_Wo2[CIND * EMBD];                  // rounded W_out
__device__ float g_Wvt[EMBD * EMBD];                  // Wv^T rounded
__device__ float g_Wvo[CIND * EMBD];                  // folded W_out·Wv

// ---------------- helpers ----------------
__device__ __forceinline__ uint32_t smem_u32(const void* p) {
    uint32_t a;
    asm("{ .reg .u64 t; cvta.to.shared.u64 t, %1; cvt.u32.u64 %0, t; }" : "=r"(a) : "l"(p));
    return a;
}
__device__ __forceinline__ uint32_t f2tf(float x) {
    uint32_t r; asm("cvt.rna.tf32.f32 %0, %1;" : "=r"(r) : "f"(x)); return r;
}
__device__ __forceinline__ float rtf(float x) { return __uint_as_float(f2tf(x)); }

#define CP_ASYNC16(dst, src) \
    asm volatile("cp.async.cg.shared.global.L2::128B [%0], [%1], 16;" \
                 :: "r"(dst), "l"(src) : "memory")
#define CP_COMMIT() asm volatile("cp.async.commit_group;" ::: "memory")
#define CP_WAIT1()  asm volatile("cp.async.wait_group 1;" ::: "memory")

__device__ __forceinline__ void ldsm_x4(uint32_t* r, uint32_t a) {
    asm volatile("ldmatrix.sync.aligned.m8n8.x4.shared.b16 {%0,%1,%2,%3}, [%4];"
                 : "=r"(r[0]), "=r"(r[1]), "=r"(r[2]), "=r"(r[3]) : "r"(a));
}
__device__ __forceinline__ void ldsm_x2(uint32_t* r, uint32_t a) {
    asm volatile("ldmatrix.sync.aligned.m8n8.x2.shared.b16 {%0,%1}, [%2];"
                 : "=r"(r[0]), "=r"(r[1]) : "r"(a));
}
__device__ __forceinline__ void mma_tf32(float* d, const uint32_t* a, const uint32_t* b) {
    asm volatile(
        "mma.sync.aligned.m16n8k8.row.col.f32.tf32.tf32.f32 "
        "{%0,%1,%2,%3}, {%4,%5,%6,%7}, {%8,%9}, {%0,%1,%2,%3};"
        : "+f"(d[0]), "+f"(d[1]), "+f"(d[2]), "+f"(d[3])
        : "r"(a[0]), "r"(a[1]), "r"(a[2]), "r"(a[3]), "r"(b[0]), "r"(b[1]));
}

// ---------------------------------------------------------------------------
// TF32 tensor-core GEMM:  C[m][n] = alpha * sum_k A[m][k] * B[n][k] (+bias)
// A, B K-major, row stride == K, PRE-ROUNDED to tf32 in memory.
// Block tile 128x128, BK=32, 3-stage cp.async pipeline, 128 threads
// (4 warps 2x2, warp tile 64x64). Single barrier per K-chunk (top barrier
// guarantees all warps finished compute(c-1) before issue(c+2) overwrites).
// MBIAS: 0 none, 1 row bias (per m), 2 batched col bias. RND: round C store.
// ---------------------------------------------------------------------------
#define STAGE_BYTES 32768
#define SMEM_BYTES  (3 * STAGE_BYTES)

template<int MBIAS, int RND>
__global__ __launch_bounds__(128, 2) void tc_gemm(
    const float* __restrict__ A, const float* __restrict__ B,
    float* __restrict__ C, const float* __restrict__ bias,
    int K, int ldc, size_t sA, size_t sB, size_t sC, size_t sBias, float alpha)
{
    extern __shared__ char smem[];
    const uint32_t sbase = smem_u32(smem);
    const int tid  = threadIdx.x;
    const int wid  = tid >> 5, lane = tid & 31;
    const int g = lane >> 2, t = lane & 3;
    const int m0w = (wid & 1) * 64;
    const int n0w = (wid >> 1) * 64;

    const float* Ab = A + blockIdx.z * sA + (size_t)(blockIdx.y * 128) * K;
    const float* Bb = B + blockIdx.z * sB + (size_t)(blockIdx.x * 128) * K;
    float*       Cb = C + blockIdx.z * sC + (size_t)(blockIdx.y * 128) * ldc
                        + blockIdx.x * 128;

    const int fr = tid >> 3;          // 0..15
    const int fq = tid & 7;

    auto issue = [&](int stage) {
        const uint32_t sa = sbase + (stage % 3) * STAGE_BYTES;
        const int k0 = stage * 32;
        #pragma unroll
        for (int i = 0; i < 8; i++) {
            const int r = fr + i * 16;
            const uint32_t dst = sa + r * 128 + ((fq ^ (r & 7)) << 4);
            CP_ASYNC16(dst, Ab + (size_t)r * K + k0 + fq * 4);
        }
        #pragma unroll
        for (int i = 0; i < 8; i++) {
            const int r = fr + i * 16;
            const uint32_t dst = sa + 16384 + r * 128 + ((fq ^ (r & 7)) << 4);
            CP_ASYNC16(dst, Bb + (size_t)r * K + k0 + fq * 4);
        }
    };

    const int aRow8 = (lane & 7) + ((lane >> 3) & 1) * 8;
    const int aCSel = (lane >> 4) & 1;
    uint32_t aBase[4]; int aPar[4];
    #pragma unroll
    for (int mt = 0; mt < 4; mt++) {
        const int r = m0w + mt * 16 + aRow8;
        aBase[mt] = (uint32_t)r * 128;
        aPar[mt]  = r & 7;
    }
    const int bCSel = (lane >> 3) & 1;
    uint32_t bBase[8]; int bPar[8];
    #pragma unroll
    for (int nt = 0; nt < 8; nt++) {
        const int r = n0w + nt * 8 + (lane & 7);
        bBase[nt] = 16384u + (uint32_t)r * 128;
        bPar[nt]  = r & 7;
    }

    float acc[4][8][4];
    #pragma unroll
    for (int mt = 0; mt < 4; mt++)
        #pragma unroll
        for (int nt = 0; nt < 8; nt++)
            #pragma unroll
            for (int i = 0; i < 4; i++) acc[mt][nt][i] = 0.0f;

    const int NC = K >> 5;
    issue(0); CP_COMMIT();
    issue(1); CP_COMMIT();

    for (int c = 0; c < NC; c++) {
        CP_WAIT1();
        __syncthreads();                    // single barrier per chunk
        if (c + 2 < NC) issue(c + 2);
        CP_COMMIT();

        const uint32_t stg = sbase + (c % 3) * STAGE_BYTES;

        #pragma unroll
        for (int ks = 0; ks < 4; ks++) {
            const int ca = 2 * ks + aCSel;
            const int cb = 2 * ks + bCSel;
            uint32_t a[4][4], b[8][2];
            #pragma unroll
            for (int mt = 0; mt < 4; mt++)
                ldsm_x4(a[mt], stg + aBase[mt] + (uint32_t)((ca ^ aPar[mt]) << 4));
            #pragma unroll
            for (int nt = 0; nt < 8; nt++)
                ldsm_x2(b[nt], stg + bBase[nt] + (uint32_t)((cb ^ bPar[nt]) << 4));
            #pragma unroll
            for (int mt = 0; mt < 4; mt++)
                #pragma unroll
                for (int nt = 0; nt < 8; nt++)
                    mma_tf32(acc[mt][nt], a[mt], b[nt]);
        }
    }

    #pragma unroll
    for (int mt = 0; mt < 4; mt++) {
        const int rm = blockIdx.y * 128 + m0w + mt * 16 + g;
        const float bv0 = (MBIAS == 1) ? __ldg(bias + rm)     : 0.0f;
        const float bv1 = (MBIAS == 1) ? __ldg(bias + rm + 8) : 0.0f;
        #pragma unroll
        for (int nt = 0; nt < 8; nt++) {
            const int cn = n0w + nt * 8 + t * 2;
            float cb0 = 0.0f, cb1 = 0.0f;
            if (MBIAS == 2) {
                const float* bb = bias + blockIdx.z * sBias + blockIdx.x * 128 + cn;
                cb0 = __ldg(bb);
                cb1 = __ldg(bb + 1);
            }
            float2 v0, v1;
            v0.x = alpha * acc[mt][nt][0] + bv0 + cb0;
            v0.y = alpha * acc[mt][nt][1] + bv0 + cb1;
            v1.x = alpha * acc[mt][nt][2] + bv1 + cb0;
            v1.y = alpha * acc[mt][nt][3] + bv1 + cb1;
            if (RND) {
                v0.x = rtf(v0.x); v0.y = rtf(v0.y);
                v1.x = rtf(v1.x); v1.y = rtf(v1.y);
            }
            const int r = m0w + mt * 16 + g;
            *reinterpret_cast<float2*>(&Cb[(size_t)r * ldc + cn]) = v0;
            *reinterpret_cast<float2*>(&Cb[(size_t)(r + 8) * ldc + cn]) = v1;
        }
    }
}

// ---------------------------------------------------------------------------
__global__ __launch_bounds__(256) void round_tf32(
    const float* __restrict__ in, float* __restrict__ out)
{
    const size_t i = (size_t)blockIdx.x * 256 + threadIdx.x;
    float4 v = reinterpret_cast<const float4*>(in)[i];
    v.x = rtf(v.x); v.y = rtf(v.y); v.z = rtf(v.z); v.w = rtf(v.w);
    reinterpret_cast<float4*>(out)[i] = v;
}

// ---------------------------------------------------------------------------
__global__ void transpose_rnd(const float* __restrict__ in, float* __restrict__ out,
                              int R, int C)
{
    __shared__ float tb[32][33];
    const int c0 = blockIdx.x * 32, r0 = blockIdx.y * 32;
    const int tx = threadIdx.x, ty = threadIdx.y;
    #pragma unroll
    for (int j = 0; j < 32; j += 8)
        tb[ty + j][tx] = in[(size_t)(r0 + ty + j) * C + c0 + tx];
    __syncthreads();
    #pragma unroll
    for (int j = 0; j < 32; j += 8)
        out[(size_t)(c0 + ty + j) * R + r0 + tx] = rtf(tb[tx][ty + j]);
}

// ---------------------------------------------------------------------------
__global__ void transpose_x(const float* __restrict__ in, float* __restrict__ out)
{
    __shared__ float tb[32][33];
    const int n0 = blockIdx.x * 32, c0 = blockIdx.y * 32;
    const float* ib = in  + (size_t)blockIdx.z * CIND * NTOK;
    float*       ob = out + (size_t)blockIdx.z * NTOK * CIND;
    const int tx = threadIdx.x, ty = threadIdx.y;
    #pragma unroll
    for (int j = 0; j < 32; j += 8)
        tb[ty + j][tx] = ib[(size_t)(c0 + ty + j) * NTOK + n0 + tx];
    __syncthreads();
    #pragma unroll
    for (int j = 0; j < 32; j += 8)
        ob[(size_t)(n0 + ty + j) * CIND + c0 + tx] = rtf(tb[tx][ty + j]);
}

// ---------------------------------------------------------------------------
__global__ __launch_bounds__(256) void gemv_bias(
    const float* __restrict__ W, const float* __restrict__ b, float* __restrict__ out)
{
    __shared__ float red[256];
    const int r = blockIdx.x;
    float s = 0.0f;
    for (int e = threadIdx.x; e < EMBD; e += 256)
        s += W[(size_t)r * EMBD + e] * b[e];
    red[threadIdx.x] = s;
    __syncthreads();
    for (int o = 128; o; o >>= 1) {
        if (threadIdx.x < o) red[threadIdx.x] += red[threadIdx.x + o];
        __syncthreads();
    }
    if (threadIdx.x == 0) out[r] = red[0];
}

// ---------------------------------------------------------------------------
__global__ __launch_bounds__(256) void beta_rows(
    const float* __restrict__ Km, const float* __restrict__ bq,
    float* __restrict__ beta, float scale)
{
    const int row = blockIdx.x * 8 + (threadIdx.x >> 5);
    const int lane = threadIdx.x & 31;
    const float* kr = Km + (size_t)row * EMBD;
    float s = 0.0f;
    #pragma unroll 4
    for (int e = lane; e < EMBD; e += 32) s += kr[e] * bq[e];
    #pragma unroll
    for (int o = 16; o; o >>= 1) s += __shfl_xor_sync(0xffffffffu, s, o);
    if (lane == 0) beta[row] = scale * s;
}

// ---------------------------------------------------------------------------
__global__ __launch_bounds__(256) void softmax_rows(
    float* __restrict__ S, float* __restrict__ SR,
    const unsigned char* __restrict__ mask)
{
    const size_t row = blockIdx.x;
    float4* p  = reinterpret_cast<float4*>(S  + row * SEQL);
    float4* pr = reinterpret_cast<float4*>(SR + row * SEQL);
    const uchar4* mp = reinterpret_cast<const uchar4*>(mask + row * SEQL);
    const int t = threadIdx.x;

    float4 v = p[t];
    uchar4 m = mp[t];
    if (m.x) v.x = -1e9f;
    if (m.y) v.y = -1e9f;
    if (m.z) v.z = -1e9f;
    if (m.w) v.w = -1e9f;

    float mx = fmaxf(fmaxf(v.x, v.y), fmaxf(v.z, v.w));
    #pragma unroll
    for (int o = 16; o; o >>= 1) mx = fmaxf(mx, __shfl_xor_sync(0xffffffffu, mx, o));
    __shared__ float sm[8];
    const int w = t >> 5;
    if ((t & 31) == 0) sm[w] = mx;
    __syncthreads();
    float rmax = sm[0];
    #pragma unroll
    for (int i = 1; i < 8; i++) rmax = fmaxf(rmax, sm[i]);

    v.x = __expf(v.x - rmax); v.y = __expf(v.y - rmax);
    v.z = __expf(v.z - rmax); v.w = __expf(v.w - rmax);

    float s = v.x + v.y + v.z + v.w;
    #pragma unroll
    for (int o = 16; o; o >>= 1) s += __shfl_xor_sync(0xffffffffu, s, o);
    __shared__ float ss[8];
    if ((t & 31) == 0) ss[w] = s;
    __syncthreads();
    float tot = 0.0f;
    #pragma unroll
    for (int i = 0; i < 8; i++) tot += ss[i];

    float inv = 1.0f / tot;
    v.x *= inv; v.y *= inv; v.z *= inv; v.w *= inv;
    p[t] = v;
    float4 r;
    r.x = rtf(v.x); r.y = rtf(v.y); r.z = rtf(v.z); r.w = rtf(v.w);
    pr[t] = r;
}

// ---------------------------------------------------------------------------
extern "C" void kernel_launch(void* const* d_in, const int* in_sizes, int n_in,
                              void* d_out, int out_size)
{
    const float* x       = (const float*)d_in[0];
    const float* content = (const float*)d_in[1];
    const unsigned char* pmask = (const unsigned char*)d_in[2];
    const float* W_in    = (const float*)d_in[3];
    const float* b_in    = (const float*)d_in[4];
    const float* Wq      = (const float*)d_in[5];
    const float* Wk      = (const float*)d_in[6];
    const float* Wv      = (const float*)d_in[7];
    const float* W_out   = (const float*)d_in[8];
    const float* b_out   = (const float*)d_in[9];

    float* out = (float*)d_out;                       // (8,512,32,32)
    float* att = out + (size_t)BATCH * CIND * NTOK;   // (8,1024,1024)

    float *xT, *Kp, *Ct, *Zt, *beta, *aR, *Ut, *Wq2, *Wk2, *Wit, *WqiT, *bq, *Wo2, *Wvt, *Wvo;
    cudaGetSymbolAddress((void**)&xT,   g_xT);
    cudaGetSymbolAddress((void**)&Kp,   g_K);
    cudaGetSymbolAddress((void**)&Ct,   g_Ct);
    cudaGetSymbolAddress((void**)&Zt,   g_Zt);
    cudaGetSymbolAddress((void**)&beta, g_beta);
    cudaGetSymbolAddress((void**)&aR,   g_aR);
    cudaGetSymbolAddress((void**)&Ut,   g_Ut);
    cudaGetSymbolAddress((void**)&Wq2,  g_Wq2);
    cudaGetSymbolAddress((void**)&Wk2,  g_Wk2);
    cudaGetSymbolAddress((void**)&Wit,  g_Wit);
    cudaGetSymbolAddress((void**)&WqiT, g_WqiT);
    cudaGetSymbolAddress((void**)&bq,   g_bq);
    cudaGetSymbolAddress((void**)&Wo2,  g_Wo2);
    cudaGetSymbolAddress((void**)&Wvt,  g_Wvt);
    cudaGetSymbolAddress((void**)&Wvo,  g_Wvo);

    cudaFuncSetAttribute(tc_gemm<0,1>, cudaFuncAttributeMaxDynamicSharedMemorySize, SMEM_BYTES);
    cudaFuncSetAttribute(tc_gemm<1,0>, cudaFuncAttributeMaxDynamicSharedMemorySize, SMEM_BYTES);
    cudaFuncSetAttribute(tc_gemm<2,0>, cudaFuncAttributeMaxDynamicSharedMemorySize, SMEM_BYTES);

    static cudaStream_t s1 = nullptr;
    static cudaEvent_t eF = nullptr, eXT = nullptr, eW = nullptr, ebq = nullptr,
                       eCt = nullptr, eZb = nullptr, eUt = nullptr, eE = nullptr;
    if (s1 == nullptr) {
        cudaStreamCreateWithFlags(&s1, cudaStreamNonBlocking);
        cudaEventCreateWithFlags(&eF,  cudaEventDisableTiming);
        cudaEventCreateWithFlags(&eXT, cudaEventDisableTiming);
        cudaEventCreateWithFlags(&eW,  cudaEventDisableTiming);
        cudaEventCreateWithFlags(&ebq, cudaEventDisableTiming);
        cudaEventCreateWithFlags(&eCt, cudaEventDisableTiming);
        cudaEventCreateWithFlags(&eZb, cudaEventDisableTiming);
        cudaEventCreateWithFlags(&eUt, cudaEventDisableTiming);
        cudaEventCreateWithFlags(&eE,  cudaEventDisableTiming);
    }

    const size_t SE  = (size_t)SEQL * EMBD;
    const size_t NS  = (size_t)NTOK * SEQL;
    const size_t NSc = (size_t)SEQL * CIND;
    const size_t XC  = (size_t)NTOK * CIND;
    const size_t CS  = (size_t)CIND * SEQL;
    const size_t CN  = (size_t)CIND * NTOK;
    const float scale = 1.0f / 32.0f;

    // NOTE on capture legality: every cudaStreamWaitEvent below is enqueued
    // AFTER its cudaEventRecord in host order. Enqueue order does not
    // serialize execution across streams.

    // ---- fork ----
    cudaEventRecord(eF, 0);
    cudaStreamWaitEvent(s1, eF, 0);

    // ======== s0 prep (enqueued first so its events exist for s1) ========
    transpose_x<<<dim3(NTOK / 32, CIND / 32, BATCH), dim3(32, 8)>>>(x, xT);
    cudaEventRecord(eXT, 0);
    round_tf32<<<(EMBD * EMBD) / 1024, 256>>>(Wq, Wq2);
    gemv_bias<<<EMBD, 256>>>(Wq, b_in, bq);
    cudaEventRecord(ebq, 0);
    transpose_rnd<<<dim3(CIND / 32, EMBD / 32), dim3(32, 8)>>>(W_in, Wit, EMBD, CIND);
    // WqiT[c][e'] = Wit[c][e]·Wq2[e'][e]
    tc_gemm<0,1><<<dim3(8, 4, 1), 128, SMEM_BYTES>>>(
        Wit, Wq2, WqiT, nullptr, EMBD, EMBD, 0, 0, 0, 0, 1.0f);
    cudaEventRecord(eW, 0);
    round_tf32<<<(CIND * EMBD) / 1024, 256>>>(W_out, Wo2);
    transpose_rnd<<<dim3(EMBD / 32, EMBD / 32), dim3(32, 8)>>>(Wv, Wvt, EMBD, EMBD);
    // Wvo[c][d] = Wo2[c][e]·Wvt[d][e]
    tc_gemm<0,1><<<dim3(8, 4, 1), 128, SMEM_BYTES>>>(
        Wo2, Wvt, Wvo, nullptr, EMBD, EMBD, 0, 0, 0, 0, 1.0f);

    // ======== s1: content -> K -> beta -> Zt ========
    round_tf32<<<(BATCH * SE) / 1024, 256, 0, s1>>>(content, Ct);
    cudaEventRecord(eCt, s1);
    round_tf32<<<(EMBD * EMBD) / 1024, 256, 0, s1>>>(Wk, Wk2);
    // K[s][e'] = Ct[s][e]·Wk2[e'][e]   (all 8 batches)
    tc_gemm<0,1><<<dim3(8, 8, BATCH), 128, SMEM_BYTES, s1>>>(
        Ct, Wk2, Kp, nullptr, EMBD, EMBD, SE, 0, SE, 0, 1.0f);
    cudaStreamWaitEvent(s1, ebq, 0);          // ebq recorded above
    beta_rows<<<(BATCH * SEQL) / 8, 256, 0, s1>>>(Kp, bq, beta, scale);
    cudaStreamWaitEvent(s1, eW, 0);           // eW recorded above
    // Zt[s][c] = Kp[s][e']·WqiT[c][e']   (all 8 batches)
    tc_gemm<0,1><<<dim3(4, 8, BATCH), 128, SMEM_BYTES, s1>>>(
        Kp, WqiT, Zt, nullptr, EMBD, CIND, SE, 0, NSc, 0, 1.0f);
    cudaEventRecord(eZb, s1);

    // ======== s0: Ut (needs Ct from s1) ========
    cudaStreamWaitEvent(0, eCt, 0);           // eCt recorded above
    tc_gemm<0,1><<<dim3(8, 4, BATCH), 128, SMEM_BYTES>>>(
        Wvo, Ct, Ut, nullptr, EMBD, SEQL, 0, SE, CS, 0, 1.0f);
    cudaEventRecord(eUt, 0);

    // ======== tail, split by batch halves across the two streams ========
    // ---- s0: batches 0..3 ----
    cudaStreamWaitEvent(0, eZb, 0);           // eZb recorded above
    tc_gemm<2,0><<<dim3(8, 8, HALFB), 128, SMEM_BYTES>>>(
        xT, Zt, att, beta, CIND, SEQL, XC, NSc, NS, SEQL, scale);
    softmax_rows<<<HALFB * NTOK, 256>>>(att, aR, pmask);
    tc_gemm<1,0><<<dim3(8, 4, HALFB), 128, SMEM_BYTES>>>(
        Ut, aR, out, b_out, SEQL, NTOK, CS, NS, CN, 0, 1.0f);

    // ---- s1: batches 4..7 ----
    cudaStreamWaitEvent(s1, eXT, 0);          // eXT recorded above
    tc_gemm<2,0><<<dim3(8, 8, HALFB), 128, SMEM_BYTES, s1>>>(
        xT + (size_t)HALFB * XC, Zt + (size_t)HALFB * NSc,
        att + (size_t)HALFB * NS, beta + (size_t)HALFB * SEQL,
        CIND, SEQL, XC, NSc, NS, SEQL, scale);
    softmax_rows<<<HALFB * NTOK, 256, 0, s1>>>(
        att + (size_t)HALFB * NS, aR + (size_t)HALFB * NS,
        pmask + (size_t)HALFB * NS);
    cudaStreamWaitEvent(s1, eUt, 0);          // eUt recorded above
    tc_gemm<1,0><<<dim3(8, 4, HALFB), 128, SMEM_BYTES, s1>>>(
        Ut + (size_t)HALFB * CS, aR + (size_t)HALFB * NS,
        out + (size_t)HALFB * CN, b_out, SEQL, NTOK, CS, NS, CN, 0, 1.0f);

    // ---- join: default stream must see s1's half-2 writes to d_out ----
    cudaEventRecord(eE, s1);
    cudaStreamWaitEvent(0, eE, 0);
}